// round 14
// baseline (speedup 1.0000x reference)
#include <cuda_runtime.h>
#include <cuda_fp16.h>
#include <stdint.h>
#include <math.h>

typedef __half f16;

// ---------------- Problem constants ----------------
#define N_NODES 4096
#define N_EDGES 32768
#define E2      (N_EDGES + N_NODES)   // with self loops = 36864
#define IN_FEAT 256
#define HID     64
#define IN_HEAD 64
#define OUT_FEAT 128
#define OUT_HEAD 5
#define F1      (IN_HEAD * HID)       // 4096
#define F2      (OUT_HEAD * OUT_FEAT) // 640
#define NEG_SLOPE 0.2f
#define GAT_EPS 1e-16f
#define KSPLIT  4

// ---------------- Device scratch ----------------
__device__ int   g_is64;
__device__ int   g_counts[N_NODES + 1];
__device__ int   g_offs[N_NODES + 1];
__device__ int   g_cursor[N_NODES];
__device__ int   g_esrc[E2];
__device__ f16   g_H1h[(size_t)N_NODES * F1];     // x @ W1 in fp16 (32 MB)
__device__ float g_A1s[(size_t)N_NODES * IN_HEAD];
__device__ float g_A1d[(size_t)N_NODES * IN_HEAD];
__device__ float g_Pk [(size_t)KSPLIT * N_NODES * F2];  // split-K partials (40 MB)
__device__ f16   g_H2h[(size_t)N_NODES * F2];     // H1a @ W2 in fp16 (5 MB)
__device__ float g_A2s[(size_t)N_NODES * OUT_HEAD];
__device__ float g_A2d[(size_t)N_NODES * OUT_HEAD];
__device__ float g_part[32 * OUT_FEAT];

// fp16 operands
__device__ f16   g_xh  [(size_t)N_NODES * IN_FEAT]; // 2 MB
__device__ f16   g_W1h [(size_t)IN_FEAT * F1];      // 2 MB
__device__ f16   g_H1ae[(size_t)N_NODES * F1];      // 32 MB (elu(agg1+b1) fp16)
__device__ f16   g_W2h [(size_t)F1 * F2];           // 5.2 MB

// ---------------- init: zero counts + int64/int32 detect ----------------
__global__ void k_init(const int* ei32) {
    int i = blockIdx.x * blockDim.x + threadIdx.x;
    if (i <= N_NODES) g_counts[i] = 0;
    if (blockIdx.x == 0 && threadIdx.x < 32) {
        int v = ei32[2 * threadIdx.x + 1];
        unsigned any = __ballot_sync(0xffffffffu, v != 0);
        if (threadIdx.x == 0) g_is64 = (any == 0) ? 1 : 0;
    }
}

__device__ __forceinline__ int load_ei(const void* ei, int idx) {
    if (g_is64) return (int)((const long long*)ei)[idx];
    return ((const int*)ei)[idx];
}

// ---------------- CSR build ----------------
__global__ void k_count(const void* ei) {
    int i = blockIdx.x * blockDim.x + threadIdx.x;
    if (i >= E2) return;
    int dst = (i < N_EDGES) ? load_ei(ei, N_EDGES + i) : (i - N_EDGES);
    atomicAdd(&g_counts[dst], 1);
}

__global__ void k_scan() {   // 1 block, 1024 threads; scan 4096 counts
    __shared__ int buf[2][1024];
    int t = threadIdx.x;
    int c0 = g_counts[4 * t], c1 = g_counts[4 * t + 1];
    int c2 = g_counts[4 * t + 2], c3 = g_counts[4 * t + 3];
    int s = c0 + c1 + c2 + c3;
    buf[0][t] = s;
    __syncthreads();
    int pin = 0;
    for (int off = 1; off < 1024; off <<= 1) {
        int v = buf[pin][t];
        if (t >= off) v += buf[pin][t - off];
        buf[pin ^ 1][t] = v;
        pin ^= 1;
        __syncthreads();
    }
    int incl = buf[pin][t];
    int base = incl - s;
    g_offs[4 * t]     = base;
    g_offs[4 * t + 1] = base + c0;
    g_offs[4 * t + 2] = base + c0 + c1;
    g_offs[4 * t + 3] = base + c0 + c1 + c2;
    g_cursor[4 * t]     = base;
    g_cursor[4 * t + 1] = base + c0;
    g_cursor[4 * t + 2] = base + c0 + c1;
    g_cursor[4 * t + 3] = base + c0 + c1 + c2;
    if (t == 1023) g_offs[N_NODES] = incl;
}

__global__ void k_scatter(const void* ei) {
    int i = blockIdx.x * blockDim.x + threadIdx.x;
    if (i >= E2) return;
    int src, dst;
    if (i < N_EDGES) { src = load_ei(ei, i); dst = load_ei(ei, N_EDGES + i); }
    else             { src = i - N_EDGES;    dst = i - N_EDGES; }
    int pos = atomicAdd(&g_cursor[dst], 1);
    g_esrc[pos] = src;
}

// ---------------- fp16 convert kernels (vectorized) ----------------
// Also zero-inits A1s/A1d and g_part each replay.
__global__ void k_cvt_x(const float* __restrict__ x) {
    int i = blockIdx.x * blockDim.x + threadIdx.x;   // 262144 threads
    float4 v = ((const float4*)x)[i];
    __half2* o = (__half2*)g_xh;
    o[2 * i]     = __floats2half2_rn(v.x, v.y);
    o[2 * i + 1] = __floats2half2_rn(v.z, v.w);
    g_A1s[i] = 0.f;                                  // N_NODES*IN_HEAD == 262144
    g_A1d[i] = 0.f;
    if (i < 32 * OUT_FEAT) g_part[i] = 0.f;
}

__global__ void k_cvt_W1(const float* __restrict__ W) {
    int i = blockIdx.x * blockDim.x + threadIdx.x;
    float4 v = ((const float4*)W)[i];
    __half2* o = (__half2*)g_W1h;
    o[2 * i]     = __floats2half2_rn(v.x, v.y);
    o[2 * i + 1] = __floats2half2_rn(v.z, v.w);
}

__global__ void k_cvt_W2(const float* __restrict__ W) {
    int i = blockIdx.x * blockDim.x + threadIdx.x;
    if (i >= (F1 * F2) / 4) return;
    float4 v = ((const float4*)W)[i];
    __half2* o = (__half2*)g_W2h;
    o[2 * i]     = __floats2half2_rn(v.x, v.y);
    o[2 * i + 1] = __floats2half2_rn(v.z, v.w);
}

// ---------------- shared GEMM geometry ----------------
#define BM 128
#define BN 128
#define BK 32
#define STG 3
#define APITCH (BK + 8)
#define BPITCH (BN + 8)
#define HG_SMEM (STG * (BM * APITCH + BK * BPITCH) * 2)

// ---------------- GEMM1: 8 warps, warp tile 64x32, fp16 out + fused dots1 ----------------
__global__ __launch_bounds__(256, 2)
void hgemm1(const f16* __restrict__ A, const f16* __restrict__ B,
            f16* __restrict__ C, int N, int aStride, int kLen,
            const float* __restrict__ att_src, const float* __restrict__ att_dst) {
    extern __shared__ f16 smbuf[];
    f16* sA = smbuf;
    f16* sB = smbuf + STG * BM * APITCH;
    int t = threadIdx.x, lane = t & 31, warp = t >> 5;
    int wm = (warp >> 2) * 64;
    int wn = (warp & 3) * 32;
    int bx = blockIdx.x, by = blockIdx.y;
    const f16* Ab = A + (size_t)(by * BM) * aStride;
    const f16* Bb = B + bx * BN;

    int a_row = t >> 2;
    int a_col = (t & 3) * 8;
    int b_row = t >> 4;
    int b_col = (t & 15) * 8;

    float acc[4][4][4];
#pragma unroll
    for (int i = 0; i < 4; i++)
#pragma unroll
        for (int j = 0; j < 4; j++)
#pragma unroll
            for (int r = 0; r < 4; r++) acc[i][j][r] = 0.f;

    auto issue = [&](int j) {
        int buf = j % STG;
        int k0 = j * BK;
        f16* pa = sA + buf * BM * APITCH;
        f16* pb = sB + buf * BK * BPITCH;
        uint32_t da0 = (uint32_t)__cvta_generic_to_shared(pa + a_row * APITCH + a_col);
        uint32_t da1 = (uint32_t)__cvta_generic_to_shared(pa + (a_row + 64) * APITCH + a_col);
        const f16* ga0 = Ab + (size_t)a_row * aStride + k0 + a_col;
        const f16* ga1 = Ab + (size_t)(a_row + 64) * aStride + k0 + a_col;
        asm volatile("cp.async.cg.shared.global [%0], [%1], 16;" :: "r"(da0), "l"(ga0));
        asm volatile("cp.async.cg.shared.global [%0], [%1], 16;" :: "r"(da1), "l"(ga1));
        uint32_t db0 = (uint32_t)__cvta_generic_to_shared(pb + b_row * BPITCH + b_col);
        uint32_t db1 = (uint32_t)__cvta_generic_to_shared(pb + (b_row + 16) * BPITCH + b_col);
        const f16* gb0 = Bb + (size_t)(k0 + b_row) * N + b_col;
        const f16* gb1 = Bb + (size_t)(k0 + b_row + 16) * N + b_col;
        asm volatile("cp.async.cg.shared.global [%0], [%1], 16;" :: "r"(db0), "l"(gb0));
        asm volatile("cp.async.cg.shared.global [%0], [%1], 16;" :: "r"(db1), "l"(gb1));
        asm volatile("cp.async.commit_group;");
    };

    int nc = kLen / BK;
    issue(0);
    if (nc > 1) issue(1);
    for (int s = 0; s < nc; s++) {
        if (s < nc - 1) { asm volatile("cp.async.wait_group 1;"); }
        else            { asm volatile("cp.async.wait_group 0;"); }
        __syncthreads();
        if (s + 2 < nc) issue(s + 2);
        int buf = s % STG;
        f16* pa = sA + buf * BM * APITCH;
        f16* pb = sB + buf * BK * BPITCH;
#pragma unroll
        for (int kk = 0; kk < 2; kk++) {
            int k = kk * 16;
            uint32_t ar[4][4], br[2][4];
#pragma unroll
            for (int mi = 0; mi < 4; mi++) {
                int row = wm + mi * 16 + (lane & 7) + ((lane >> 3) & 1) * 8;
                int col = k + (lane >> 4) * 8;
                uint32_t addr = (uint32_t)__cvta_generic_to_shared(pa + row * APITCH + col);
                asm volatile("ldmatrix.sync.aligned.m8n8.x4.shared.b16 {%0,%1,%2,%3}, [%4];"
                             : "=r"(ar[mi][0]), "=r"(ar[mi][1]), "=r"(ar[mi][2]), "=r"(ar[mi][3])
                             : "r"(addr));
            }
#pragma unroll
            for (int n2 = 0; n2 < 2; n2++) {
                int rrow = k + (lane & 7) + ((lane >> 3) & 1) * 8;
                int rcol = wn + n2 * 16 + (lane >> 4) * 8;
                uint32_t addr = (uint32_t)__cvta_generic_to_shared(pb + rrow * BPITCH + rcol);
                asm volatile("ldmatrix.sync.aligned.m8n8.x4.trans.shared.b16 {%0,%1,%2,%3}, [%4];"
                             : "=r"(br[n2][0]), "=r"(br[n2][1]), "=r"(br[n2][2]), "=r"(br[n2][3])
                             : "r"(addr));
            }
#pragma unroll
            for (int mi = 0; mi < 4; mi++)
#pragma unroll
                for (int ni = 0; ni < 4; ni++) {
                    uint32_t b0 = br[ni >> 1][(ni & 1) * 2];
                    uint32_t b1 = br[ni >> 1][(ni & 1) * 2 + 1];
                    asm volatile(
                        "mma.sync.aligned.m16n8k16.row.col.f32.f16.f16.f32 "
                        "{%0,%1,%2,%3}, {%4,%5,%6,%7}, {%8,%9}, {%0,%1,%2,%3};"
                        : "+f"(acc[mi][ni][0]), "+f"(acc[mi][ni][1]),
                          "+f"(acc[mi][ni][2]), "+f"(acc[mi][ni][3])
                        : "r"(ar[mi][0]), "r"(ar[mi][1]), "r"(ar[mi][2]), "r"(ar[mi][3]),
                          "r"(b0), "r"(b1));
                }
        }
        __syncthreads();
    }
    f16* Cb = C + (size_t)(by * BM + wm) * N + bx * BN + wn;
#pragma unroll
    for (int mi = 0; mi < 4; mi++)
#pragma unroll
        for (int ni = 0; ni < 4; ni++) {
            int r0 = mi * 16 + (lane >> 2);
            int c0 = ni * 8 + (lane & 3) * 2;
            *(__half2*)(Cb + (size_t)r0 * N + c0)       = __floats2half2_rn(acc[mi][ni][0], acc[mi][ni][1]);
            *(__half2*)(Cb + (size_t)(r0 + 8) * N + c0) = __floats2half2_rn(acc[mi][ni][2], acc[mi][ni][3]);
        }
    // ---- fused layer-1 attention dots (warp's 32 cols lie in one head) ----
    int gcol0 = bx * BN + wn;
    int head = gcol0 >> 6;               // HID = 64
    const float* as = att_src + head * HID;
    const float* ad = att_dst + head * HID;
    int cbase = (gcol0 & 63) + (lane & 3) * 2;
#pragma unroll
    for (int mi = 0; mi < 4; mi++) {
#pragma unroll
        for (int rr = 0; rr < 2; rr++) {
            float ssum = 0.f, dsum = 0.f;
#pragma unroll
            for (int ni = 0; ni < 4; ni++) {
#pragma unroll
                for (int q = 0; q < 2; q++) {
                    int ch = cbase + ni * 8 + q;
                    float v = acc[mi][ni][rr * 2 + q];
                    ssum += v * as[ch];
                    dsum += v * ad[ch];
                }
            }
            ssum += __shfl_xor_sync(0xffffffffu, ssum, 1);
            ssum += __shfl_xor_sync(0xffffffffu, ssum, 2);
            dsum += __shfl_xor_sync(0xffffffffu, dsum, 1);
            dsum += __shfl_xor_sync(0xffffffffu, dsum, 2);
            if ((lane & 3) == 0) {
                int n = by * BM + wm + mi * 16 + (lane >> 2) + rr * 8;
                atomicAdd(&g_A1s[n * IN_HEAD + head], ssum);
                atomicAdd(&g_A1d[n * IN_HEAD + head], dsum);
            }
        }
    }
}

// ---------------- GEMM2: 4 warps, warp tile 64x64, fp32 out; row-half via mOff ----------------
__global__ __launch_bounds__(128, 2)
void hgemm2(const f16* __restrict__ A, const f16* __restrict__ B,
            float* __restrict__ Cbase, size_t cStride,
            int N, int aStride, int kLen, int mOff) {
    extern __shared__ f16 smbuf[];
    f16* sA = smbuf;
    f16* sB = smbuf + STG * BM * APITCH;
    int t = threadIdx.x, lane = t & 31, warp = t >> 5;
    int wm = (warp >> 1) * 64;
    int wn = (warp & 1) * 64;
    int bx = blockIdx.x, by = blockIdx.y, bz = blockIdx.z;
    int rowBase = mOff + by * BM;
    int kOff = bz * kLen;
    const f16* Ab = A + (size_t)rowBase * aStride + kOff;
    const f16* Bb = B + (size_t)kOff * N + bx * BN;

    float acc[4][8][4];
#pragma unroll
    for (int i = 0; i < 4; i++)
#pragma unroll
        for (int j = 0; j < 8; j++)
#pragma unroll
            for (int r = 0; r < 4; r++) acc[i][j][r] = 0.f;

    auto issue = [&](int j) {
        int buf = j % STG;
        int k0 = j * BK;
        f16* pa = sA + buf * BM * APITCH;
        f16* pb = sB + buf * BK * BPITCH;
#pragma unroll
        for (int i = 0; i < 4; i++) {
            int id = t + 128 * i;
            int row = id >> 2, c = (id & 3) * 8;
            uint32_t d = (uint32_t)__cvta_generic_to_shared(pa + row * APITCH + c);
            const f16* g = Ab + (size_t)row * aStride + k0 + c;
            asm volatile("cp.async.cg.shared.global [%0], [%1], 16;" :: "r"(d), "l"(g));
        }
#pragma unroll
        for (int i = 0; i < 4; i++) {
            int id = t + 128 * i;
            int row = id >> 4, c = (id & 15) * 8;
            uint32_t d = (uint32_t)__cvta_generic_to_shared(pb + row * BPITCH + c);
            const f16* g = Bb + (size_t)(k0 + row) * N + c;
            asm volatile("cp.async.cg.shared.global [%0], [%1], 16;" :: "r"(d), "l"(g));
        }
        asm volatile("cp.async.commit_group;");
    };

    int nc = kLen / BK;
    issue(0);
    if (nc > 1) issue(1);
    for (int s = 0; s < nc; s++) {
        if (s < nc - 1) { asm volatile("cp.async.wait_group 1;"); }
        else            { asm volatile("cp.async.wait_group 0;"); }
        __syncthreads();
        if (s + 2 < nc) issue(s + 2);
        int buf = s % STG;
        f16* pa = sA + buf * BM * APITCH;
        f16* pb = sB + buf * BK * BPITCH;
#pragma unroll
        for (int kk = 0; kk < 2; kk++) {
            int k = kk * 16;
            uint32_t ar[4][4], br[4][4];
#pragma unroll
            for (int mi = 0; mi < 4; mi++) {
                int row = wm + mi * 16 + (lane & 7) + ((lane >> 3) & 1) * 8;
                int col = k + (lane >> 4) * 8;
                uint32_t addr = (uint32_t)__cvta_generic_to_shared(pa + row * APITCH + col);
                asm volatile("ldmatrix.sync.aligned.m8n8.x4.shared.b16 {%0,%1,%2,%3}, [%4];"
                             : "=r"(ar[mi][0]), "=r"(ar[mi][1]), "=r"(ar[mi][2]), "=r"(ar[mi][3])
                             : "r"(addr));
            }
#pragma unroll
            for (int n2 = 0; n2 < 4; n2++) {
                int rrow = k + (lane & 7) + ((lane >> 3) & 1) * 8;
                int rcol = wn + n2 * 16 + (lane >> 4) * 8;
                uint32_t addr = (uint32_t)__cvta_generic_to_shared(pb + rrow * BPITCH + rcol);
                asm volatile("ldmatrix.sync.aligned.m8n8.x4.trans.shared.b16 {%0,%1,%2,%3}, [%4];"
                             : "=r"(br[n2][0]), "=r"(br[n2][1]), "=r"(br[n2][2]), "=r"(br[n2][3])
                             : "r"(addr));
            }
#pragma unroll
            for (int mi = 0; mi < 4; mi++)
#pragma unroll
                for (int ni = 0; ni < 8; ni++) {
                    uint32_t b0 = br[ni >> 1][(ni & 1) * 2];
                    uint32_t b1 = br[ni >> 1][(ni & 1) * 2 + 1];
                    asm volatile(
                        "mma.sync.aligned.m16n8k16.row.col.f32.f16.f16.f32 "
                        "{%0,%1,%2,%3}, {%4,%5,%6,%7}, {%8,%9}, {%0,%1,%2,%3};"
                        : "+f"(acc[mi][ni][0]), "+f"(acc[mi][ni][1]),
                          "+f"(acc[mi][ni][2]), "+f"(acc[mi][ni][3])
                        : "r"(ar[mi][0]), "r"(ar[mi][1]), "r"(ar[mi][2]), "r"(ar[mi][3]),
                          "r"(b0), "r"(b1));
                }
        }
        __syncthreads();
    }
    float* Cb = Cbase + bz * cStride + (size_t)(rowBase + wm) * N + bx * BN + wn;
#pragma unroll
    for (int mi = 0; mi < 4; mi++)
#pragma unroll
        for (int ni = 0; ni < 8; ni++) {
            int r0 = mi * 16 + (lane >> 2);
            int c0 = ni * 8 + (lane & 3) * 2;
            *(float2*)(Cb + (size_t)r0 * N + c0)       = make_float2(acc[mi][ni][0], acc[mi][ni][1]);
            *(float2*)(Cb + (size_t)(r0 + 8) * N + c0) = make_float2(acc[mi][ni][2], acc[mi][ni][3]);
        }
}

// ---------------- fused split-K reduce (4-way) + fp16 H2 store + layer-2 dots ----------------
__global__ void k_red_dots2(const float* __restrict__ att_src, const float* __restrict__ att_dst) {
    int n = blockIdx.x;
    int t = threadIdx.x, lane = t & 31, h = t >> 5;
    const size_t stride4 = (size_t)N_NODES * F2 / 4;
    const float4* p = (const float4*)g_Pk + (size_t)n * (F2 / 4);

    float4 v = p[t];
#pragma unroll
    for (int z = 1; z < KSPLIT; z++) {
        float4 a = p[z * stride4 + t];
        v.x += a.x; v.y += a.y; v.z += a.z; v.w += a.w;
    }
    __half2* h2 = (__half2*)g_H2h + (size_t)n * (F2 / 2);
    h2[2 * t]     = __floats2half2_rn(v.x, v.y);
    h2[2 * t + 1] = __floats2half2_rn(v.z, v.w);

    int c0 = lane * 4;
    const float* as = att_src + h * OUT_FEAT + c0;
    const float* ad = att_dst + h * OUT_FEAT + c0;
    float sa = v.x * as[0] + v.y * as[1] + v.z * as[2] + v.w * as[3];
    float sd = v.x * ad[0] + v.y * ad[1] + v.z * ad[2] + v.w * ad[3];
#pragma unroll
    for (int o = 16; o > 0; o >>= 1) {
        sa += __shfl_xor_sync(0xffffffffu, sa, o);
        sd += __shfl_xor_sync(0xffffffffu, sd, o);
    }
    if (lane == 0) {
        g_A2s[n * OUT_HEAD + h] = sa;
        g_A2d[n * OUT_HEAD + h] = sd;
    }
}

__device__ __forceinline__ float leaky(float x) { return x > 0.f ? x : NEG_SLOPE * x; }

// ---------------- Layer-1 softmax + aggregation + bias + elu -> fp16 (node half) ----------------
__global__ void k_agg1(const float* __restrict__ b1, int nodeBase) {
    int n = nodeBase + blockIdx.x;
    int t = threadIdx.x;
    int h = t & 63, slot = t >> 6;
    int beg = g_offs[n], end = g_offs[n + 1];
    float adst = g_A1d[n * IN_HEAD + h];

    __shared__ float red[4][64];
    __shared__ float sm_m[64], sm_inv[64];
    __shared__ int   srcb[32];
    __shared__ float alpha[32][64];

    float mx = -1e30f;
    for (int j = beg + slot; j < end; j += 4) {
        int s = g_esrc[j];
        mx = fmaxf(mx, leaky(g_A1s[s * IN_HEAD + h] + adst));
    }
    red[slot][h] = mx;
    __syncthreads();
    if (slot == 0) {
        sm_m[h] = fmaxf(fmaxf(red[0][h], red[1][h]), fmaxf(red[2][h], red[3][h]));
    }
    __syncthreads();
    float M = sm_m[h];

    float sum = 0.f;
    for (int j = beg + slot; j < end; j += 4) {
        int s = g_esrc[j];
        sum += expf(leaky(g_A1s[s * IN_HEAD + h] + adst) - M);
    }
    red[slot][h] = sum;
    __syncthreads();
    if (slot == 0) {
        float d = red[0][h] + red[1][h] + red[2][h] + red[3][h];
        sm_inv[h] = 1.0f / (d + GAT_EPS);
    }
    __syncthreads();
    float INV = sm_inv[h];

    int c2 = t & 31, g = t >> 5;
    float2 acc[8];
#pragma unroll
    for (int k = 0; k < 8; k++) acc[k] = make_float2(0.f, 0.f);

    for (int jb = beg; jb < end; jb += 32) {
        int cnt = min(32, end - jb);
        if (t < cnt) srcb[t] = g_esrc[jb + t];
        __syncthreads();
        for (int j = slot; j < cnt; j += 4) {
            int s = srcb[j];
            float e = leaky(g_A1s[s * IN_HEAD + h] + adst);
            alpha[j][h] = expf(e - M) * INV;
        }
        __syncthreads();
        int j = 0;
        for (; j + 3 < cnt; j += 4) {
            const __half2* r0 = (const __half2*)(g_H1h + (size_t)srcb[j] * F1);
            const __half2* r1 = (const __half2*)(g_H1h + (size_t)srcb[j + 1] * F1);
            const __half2* r2 = (const __half2*)(g_H1h + (size_t)srcb[j + 2] * F1);
            const __half2* r3 = (const __half2*)(g_H1h + (size_t)srcb[j + 3] * F1);
#pragma unroll
            for (int k = 0; k < 8; k++) {
                int hh = g * 8 + k;
                int idx = hh * 32 + c2;
                float2 f0 = __half22float2(r0[idx]);
                float2 f1 = __half22float2(r1[idx]);
                float2 f2 = __half22float2(r2[idx]);
                float2 f3 = __half22float2(r3[idx]);
                float a0 = alpha[j][hh], a1 = alpha[j + 1][hh];
                float a2 = alpha[j + 2][hh], a3 = alpha[j + 3][hh];
                acc[k].x += a0 * f0.x + a1 * f1.x + a2 * f2.x + a3 * f3.x;
                acc[k].y += a0 * f0.y + a1 * f1.y + a2 * f2.y + a3 * f3.y;
            }
        }
        for (; j < cnt; j++) {
            const __half2* row = (const __half2*)(g_H1h + (size_t)srcb[j] * F1);
#pragma unroll
            for (int k = 0; k < 8; k++) {
                int hh = g * 8 + k;
                float2 f = __half22float2(row[hh * 32 + c2]);
                float a = alpha[j][hh];
                acc[k].x += a * f.x;
                acc[k].y += a * f.y;
            }
        }
        __syncthreads();
    }
    __half2* rowo = (__half2*)(g_H1ae + (size_t)n * F1);
#pragma unroll
    for (int k = 0; k < 8; k++) {
        int hh = g * 8 + k;
        float vx = acc[k].x + b1[hh * HID + 2 * c2];
        float vy = acc[k].y + b1[hh * HID + 2 * c2 + 1];
        vx = vx > 0.f ? vx : expm1f(vx);
        vy = vy > 0.f ? vy : expm1f(vy);
        rowo[hh * 32 + c2] = __floats2half2_rn(vx, vy);
    }
}

// ---------------- Layer-2 softmax + aggregation + head-mean + bias + partial node-sum ----------------
__global__ void k_agg2(const float* __restrict__ b2) {
    int n = blockIdx.x;
    int t = threadIdx.x;
    int beg = g_offs[n], end = g_offs[n + 1];

    __shared__ float sm_m[OUT_HEAD], sm_inv[OUT_HEAD];
    __shared__ int   srcb[16];
    __shared__ float alpha[16][OUT_HEAD];

    if (t < OUT_HEAD) {
        float adst = g_A2d[n * OUT_HEAD + t];
        float mx = -1e30f;
        for (int j = beg; j < end; j++)
            mx = fmaxf(mx, leaky(g_A2s[g_esrc[j] * OUT_HEAD + t] + adst));
        float sum = 0.f;
        for (int j = beg; j < end; j++)
            sum += expf(leaky(g_A2s[g_esrc[j] * OUT_HEAD + t] + adst) - mx);
        sm_m[t] = mx;
        sm_inv[t] = 1.0f / (sum + GAT_EPS);
    }
    __syncthreads();

    float acc[OUT_HEAD] = {0.f, 0.f, 0.f, 0.f, 0.f};
    for (int jb = beg; jb < end; jb += 16) {
        int cnt = min(16, end - jb);
        if (t < cnt) srcb[t] = g_esrc[jb + t];
        __syncthreads();
        if (t < cnt * OUT_HEAD) {
            int j = t / OUT_HEAD, hh = t % OUT_HEAD;
            int s = srcb[j];
            float e = leaky(g_A2s[s * OUT_HEAD + hh] + g_A2d[n * OUT_HEAD + hh]);
            alpha[j][hh] = expf(e - sm_m[hh]) * sm_inv[hh];
        }
        __syncthreads();
        for (int j = 0; j < cnt; j++) {
            const f16* row = g_H2h + (size_t)srcb[j] * F2;
#pragma unroll
            for (int hh = 0; hh < OUT_HEAD; hh++)
                acc[hh] += alpha[j][hh] * __half2float(row[hh * OUT_FEAT + t]);
        }
        __syncthreads();
    }
    float o = (acc[0] + acc[1] + acc[2] + acc[3] + acc[4]) * 0.2f + b2[t];
    atomicAdd(&g_part[(n & 31) * OUT_FEAT + t], o);
}

// ---------------- Final node-mean + tanh ----------------
__global__ void k_final(float* __restrict__ out) {
    int c = threadIdx.x;
    float s = 0.f;
#pragma unroll
    for (int b = 0; b < 32; b++) s += g_part[b * OUT_FEAT + c];
    out[c] = tanhf(s / (float)N_NODES);
}

// ---------------- Launch ----------------
extern "C" void kernel_launch(void* const* d_in, const int* in_sizes, int n_in,
                              void* d_out, int out_size) {
    const float* x        = (const float*)d_in[0];
    const void*  ei       = d_in[1];
    const float* W1       = (const float*)d_in[2];
    const float* att_src1 = (const float*)d_in[3];
    const float* att_dst1 = (const float*)d_in[4];
    const float* b1       = (const float*)d_in[5];
    const float* W2       = (const float*)d_in[6];
    const float* att_src2 = (const float*)d_in[7];
    const float* att_dst2 = (const float*)d_in[8];
    const float* b2       = (const float*)d_in[9];
    float* out = (float*)d_out;

    static f16*   s_H1h  = nullptr;
    static float* s_Pk   = nullptr;
    static f16*   s_xh   = nullptr;
    static f16*   s_W1h  = nullptr;
    static f16*   s_H1ae = nullptr;
    static f16*   s_W2h  = nullptr;
    static cudaStream_t s2 = nullptr;
    static cudaEvent_t  evFork = nullptr, evJoin = nullptr, evG1 = nullptr, evA1 = nullptr;
    static bool   s_init = false;
    if (!s_init) {
        cudaGetSymbolAddress((void**)&s_H1h,  g_H1h);
        cudaGetSymbolAddress((void**)&s_Pk,   g_Pk);
        cudaGetSymbolAddress((void**)&s_xh,   g_xh);
        cudaGetSymbolAddress((void**)&s_W1h,  g_W1h);
        cudaGetSymbolAddress((void**)&s_H1ae, g_H1ae);
        cudaGetSymbolAddress((void**)&s_W2h,  g_W2h);
        cudaFuncSetAttribute(hgemm1, cudaFuncAttributeMaxDynamicSharedMemorySize, HG_SMEM);
        cudaFuncSetAttribute(hgemm2, cudaFuncAttributeMaxDynamicSharedMemorySize, HG_SMEM);
        cudaStreamCreateWithFlags(&s2, cudaStreamNonBlocking);
        cudaEventCreateWithFlags(&evFork, cudaEventDisableTiming);
        cudaEventCreateWithFlags(&evJoin, cudaEventDisableTiming);
        cudaEventCreateWithFlags(&evG1,   cudaEventDisableTiming);
        cudaEventCreateWithFlags(&evA1,   cudaEventDisableTiming);
        s_init = true;
    }

    const int HALF = N_NODES / 2;   // 2048

    // ---- fork: CSR chain + W2 convert on s2, concurrent with GEMM1 path ----
    cudaEventRecord(evFork, 0);
    cudaStreamWaitEvent(s2, evFork, 0);

    k_init   <<<(N_NODES + 256) / 256, 256, 0, s2>>>((const int*)ei);
    k_count  <<<(E2 + 255) / 256, 256, 0, s2>>>(ei);
    k_scan   <<<1, 1024, 0, s2>>>();
    k_scatter<<<(E2 + 255) / 256, 256, 0, s2>>>(ei);
    k_cvt_W2 <<<((F1 * F2 / 4) + 255) / 256, 256, 0, s2>>>(W2);
    cudaEventRecord(evJoin, s2);

    // ---- main stream: GEMM1 path (k_cvt_x zeroes A1s/A1d/g_part) ----
    k_cvt_x <<<(N_NODES * IN_FEAT / 4) / 256, 256>>>(x);
    k_cvt_W1<<<(IN_FEAT * F1 / 4) / 256, 256>>>(W1);

    hgemm1<<<dim3(F1 / BN, N_NODES / BM), 256, HG_SMEM>>>(
        s_xh, s_W1h, s_H1h, F1, IN_FEAT, IN_FEAT, att_src1, att_dst1);
    cudaEventRecord(evG1, 0);    // H1h + A1s/A1d complete

    // ---- join: agg1 needs CSR (s2) ----
    cudaStreamWaitEvent(0, evJoin, 0);

    // agg1 half 0 on main
    k_agg1<<<HALF, 256>>>(b1, 0);

    // agg1 half 1 on s2 (needs evG1 from main; CSR already in-stream on s2)
    cudaStreamWaitEvent(s2, evG1, 0);
    k_agg1<<<HALF, 256, 0, s2>>>(b1, HALF);
    cudaEventRecord(evA1, s2);

    // GEMM2 half 0 (rows 0..2047) on main — overlaps agg1 half 1 on s2
    hgemm2<<<dim3(F2 / BN, HALF / BM, KSPLIT), 128, HG_SMEM>>>(
        s_H1ae, s_W2h, s_Pk, (size_t)N_NODES * F2, F2, F1, F1 / KSPLIT, 0);

    // GEMM2 half 1 after agg1 half 1 completes
    cudaStreamWaitEvent(0, evA1, 0);
    hgemm2<<<dim3(F2 / BN, HALF / BM, KSPLIT), 128, HG_SMEM>>>(
        s_H1ae, s_W2h, s_Pk, (size_t)N_NODES * F2, F2, F1, F1 / KSPLIT, HALF);

    // fused: H2h = sum(Pk) (fp16) + layer-2 attention dots
    k_red_dots2<<<N_NODES, 160>>>(att_src2, att_dst2);

    // agg2 with fused partial node-sum (atomicAdd into g_part)
    k_agg2<<<N_NODES, 128>>>(b2);

    k_final<<<1, 128>>>(out);
}

// round 15
// speedup vs baseline: 1.6326x; 1.6326x over previous
#include <cuda_runtime.h>
#include <cuda_fp16.h>
#include <stdint.h>
#include <math.h>

typedef __half f16;

// ---------------- Problem constants ----------------
#define N_NODES 4096
#define N_EDGES 32768
#define E2      (N_EDGES + N_NODES)   // with self loops = 36864
#define IN_FEAT 256
#define HID     64
#define IN_HEAD 64
#define OUT_FEAT 128
#define OUT_HEAD 5
#define F1      (IN_HEAD * HID)       // 4096
#define F2      (OUT_HEAD * OUT_FEAT) // 640
#define NEG_SLOPE 0.2f
#define GAT_EPS 1e-16f
#define KSPLIT  4

// ---------------- Device scratch ----------------
__device__ int   g_is64;
__device__ int   g_counts[N_NODES + 1];
__device__ int   g_offs[N_NODES + 1];
__device__ int   g_cursor[N_NODES];
__device__ int   g_esrc[E2];
__device__ f16   g_H1h[(size_t)N_NODES * F1];     // x @ W1 in fp16 (32 MB)
__device__ float g_A1s[(size_t)N_NODES * IN_HEAD];
__device__ float g_A1d[(size_t)N_NODES * IN_HEAD];
__device__ float g_Pk [(size_t)KSPLIT * N_NODES * F2];  // split-K partials (40 MB)
__device__ f16   g_H2h[(size_t)N_NODES * F2];     // H1a @ W2 in fp16 (5 MB)
__device__ float g_A2s[(size_t)N_NODES * OUT_HEAD];
__device__ float g_A2d[(size_t)N_NODES * OUT_HEAD];
__device__ float g_part[32 * OUT_FEAT];

// fp16 operands
__device__ f16   g_xh  [(size_t)N_NODES * IN_FEAT]; // 2 MB
__device__ f16   g_W1h [(size_t)IN_FEAT * F1];      // 2 MB
__device__ f16   g_H1ae[(size_t)N_NODES * F1];      // 32 MB (elu(agg1+b1) fp16)
__device__ f16   g_W2h [(size_t)F1 * F2];           // 5.2 MB

// ---------------- init: zero counts + int64/int32 detect ----------------
__global__ void k_init(const int* ei32) {
    int i = blockIdx.x * blockDim.x + threadIdx.x;
    if (i <= N_NODES) g_counts[i] = 0;
    if (blockIdx.x == 0 && threadIdx.x < 32) {
        int v = ei32[2 * threadIdx.x + 1];
        unsigned any = __ballot_sync(0xffffffffu, v != 0);
        if (threadIdx.x == 0) g_is64 = (any == 0) ? 1 : 0;
    }
}

__device__ __forceinline__ int load_ei(const void* ei, int idx) {
    if (g_is64) return (int)((const long long*)ei)[idx];
    return ((const int*)ei)[idx];
}

// ---------------- CSR build ----------------
__global__ void k_count(const void* ei) {
    int i = blockIdx.x * blockDim.x + threadIdx.x;
    if (i >= E2) return;
    int dst = (i < N_EDGES) ? load_ei(ei, N_EDGES + i) : (i - N_EDGES);
    atomicAdd(&g_counts[dst], 1);
}

__global__ void k_scan() {   // 1 block, 1024 threads; scan 4096 counts
    __shared__ int buf[2][1024];
    int t = threadIdx.x;
    int c0 = g_counts[4 * t], c1 = g_counts[4 * t + 1];
    int c2 = g_counts[4 * t + 2], c3 = g_counts[4 * t + 3];
    int s = c0 + c1 + c2 + c3;
    buf[0][t] = s;
    __syncthreads();
    int pin = 0;
    for (int off = 1; off < 1024; off <<= 1) {
        int v = buf[pin][t];
        if (t >= off) v += buf[pin][t - off];
        buf[pin ^ 1][t] = v;
        pin ^= 1;
        __syncthreads();
    }
    int incl = buf[pin][t];
    int base = incl - s;
    g_offs[4 * t]     = base;
    g_offs[4 * t + 1] = base + c0;
    g_offs[4 * t + 2] = base + c0 + c1;
    g_offs[4 * t + 3] = base + c0 + c1 + c2;
    g_cursor[4 * t]     = base;
    g_cursor[4 * t + 1] = base + c0;
    g_cursor[4 * t + 2] = base + c0 + c1;
    g_cursor[4 * t + 3] = base + c0 + c1 + c2;
    if (t == 1023) g_offs[N_NODES] = incl;
}

__global__ void k_scatter(const void* ei) {
    int i = blockIdx.x * blockDim.x + threadIdx.x;
    if (i >= E2) return;
    int src, dst;
    if (i < N_EDGES) { src = load_ei(ei, i); dst = load_ei(ei, N_EDGES + i); }
    else             { src = i - N_EDGES;    dst = i - N_EDGES; }
    int pos = atomicAdd(&g_cursor[dst], 1);
    g_esrc[pos] = src;
}

// ---------------- fp16 convert kernels (vectorized) ----------------
// Also zero-inits A1s/A1d and g_part each replay.
__global__ void k_cvt_x(const float* __restrict__ x) {
    int i = blockIdx.x * blockDim.x + threadIdx.x;   // 262144 threads
    float4 v = ((const float4*)x)[i];
    __half2* o = (__half2*)g_xh;
    o[2 * i]     = __floats2half2_rn(v.x, v.y);
    o[2 * i + 1] = __floats2half2_rn(v.z, v.w);
    g_A1s[i] = 0.f;                                  // N_NODES*IN_HEAD == 262144
    g_A1d[i] = 0.f;
    if (i < 32 * OUT_FEAT) g_part[i] = 0.f;
}

__global__ void k_cvt_W1(const float* __restrict__ W) {
    int i = blockIdx.x * blockDim.x + threadIdx.x;
    float4 v = ((const float4*)W)[i];
    __half2* o = (__half2*)g_W1h;
    o[2 * i]     = __floats2half2_rn(v.x, v.y);
    o[2 * i + 1] = __floats2half2_rn(v.z, v.w);
}

__global__ void k_cvt_W2(const float* __restrict__ W) {
    int i = blockIdx.x * blockDim.x + threadIdx.x;
    if (i >= (F1 * F2) / 4) return;
    float4 v = ((const float4*)W)[i];
    __half2* o = (__half2*)g_W2h;
    o[2 * i]     = __floats2half2_rn(v.x, v.y);
    o[2 * i + 1] = __floats2half2_rn(v.z, v.w);
}

// ---------------- shared GEMM geometry ----------------
#define BM 128
#define BN 128
#define BK 32
#define STG 3
#define APITCH (BK + 8)
#define BPITCH (BN + 8)
#define HG_SMEM (STG * (BM * APITCH + BK * BPITCH) * 2)

// ---------------- GEMM1: 8 warps, warp tile 64x32, fp16 out + fused dots1 ----------------
__global__ __launch_bounds__(256, 2)
void hgemm1(const f16* __restrict__ A, const f16* __restrict__ B,
            f16* __restrict__ C, int N, int aStride, int kLen,
            const float* __restrict__ att_src, const float* __restrict__ att_dst) {
    extern __shared__ f16 smbuf[];
    f16* sA = smbuf;
    f16* sB = smbuf + STG * BM * APITCH;
    int t = threadIdx.x, lane = t & 31, warp = t >> 5;
    int wm = (warp >> 2) * 64;
    int wn = (warp & 3) * 32;
    int bx = blockIdx.x, by = blockIdx.y;
    const f16* Ab = A + (size_t)(by * BM) * aStride;
    const f16* Bb = B + bx * BN;

    int a_row = t >> 2;
    int a_col = (t & 3) * 8;
    int b_row = t >> 4;
    int b_col = (t & 15) * 8;

    float acc[4][4][4];
#pragma unroll
    for (int i = 0; i < 4; i++)
#pragma unroll
        for (int j = 0; j < 4; j++)
#pragma unroll
            for (int r = 0; r < 4; r++) acc[i][j][r] = 0.f;

    auto issue = [&](int j) {
        int buf = j % STG;
        int k0 = j * BK;
        f16* pa = sA + buf * BM * APITCH;
        f16* pb = sB + buf * BK * BPITCH;
        uint32_t da0 = (uint32_t)__cvta_generic_to_shared(pa + a_row * APITCH + a_col);
        uint32_t da1 = (uint32_t)__cvta_generic_to_shared(pa + (a_row + 64) * APITCH + a_col);
        const f16* ga0 = Ab + (size_t)a_row * aStride + k0 + a_col;
        const f16* ga1 = Ab + (size_t)(a_row + 64) * aStride + k0 + a_col;
        asm volatile("cp.async.cg.shared.global [%0], [%1], 16;" :: "r"(da0), "l"(ga0));
        asm volatile("cp.async.cg.shared.global [%0], [%1], 16;" :: "r"(da1), "l"(ga1));
        uint32_t db0 = (uint32_t)__cvta_generic_to_shared(pb + b_row * BPITCH + b_col);
        uint32_t db1 = (uint32_t)__cvta_generic_to_shared(pb + (b_row + 16) * BPITCH + b_col);
        const f16* gb0 = Bb + (size_t)(k0 + b_row) * N + b_col;
        const f16* gb1 = Bb + (size_t)(k0 + b_row + 16) * N + b_col;
        asm volatile("cp.async.cg.shared.global [%0], [%1], 16;" :: "r"(db0), "l"(gb0));
        asm volatile("cp.async.cg.shared.global [%0], [%1], 16;" :: "r"(db1), "l"(gb1));
        asm volatile("cp.async.commit_group;");
    };

    int nc = kLen / BK;
    issue(0);
    if (nc > 1) issue(1);
    for (int s = 0; s < nc; s++) {
        if (s < nc - 1) { asm volatile("cp.async.wait_group 1;"); }
        else            { asm volatile("cp.async.wait_group 0;"); }
        __syncthreads();
        if (s + 2 < nc) issue(s + 2);
        int buf = s % STG;
        f16* pa = sA + buf * BM * APITCH;
        f16* pb = sB + buf * BK * BPITCH;
#pragma unroll
        for (int kk = 0; kk < 2; kk++) {
            int k = kk * 16;
            uint32_t ar[4][4], br[2][4];
#pragma unroll
            for (int mi = 0; mi < 4; mi++) {
                int row = wm + mi * 16 + (lane & 7) + ((lane >> 3) & 1) * 8;
                int col = k + (lane >> 4) * 8;
                uint32_t addr = (uint32_t)__cvta_generic_to_shared(pa + row * APITCH + col);
                asm volatile("ldmatrix.sync.aligned.m8n8.x4.shared.b16 {%0,%1,%2,%3}, [%4];"
                             : "=r"(ar[mi][0]), "=r"(ar[mi][1]), "=r"(ar[mi][2]), "=r"(ar[mi][3])
                             : "r"(addr));
            }
#pragma unroll
            for (int n2 = 0; n2 < 2; n2++) {
                int rrow = k + (lane & 7) + ((lane >> 3) & 1) * 8;
                int rcol = wn + n2 * 16 + (lane >> 4) * 8;
                uint32_t addr = (uint32_t)__cvta_generic_to_shared(pb + rrow * BPITCH + rcol);
                asm volatile("ldmatrix.sync.aligned.m8n8.x4.trans.shared.b16 {%0,%1,%2,%3}, [%4];"
                             : "=r"(br[n2][0]), "=r"(br[n2][1]), "=r"(br[n2][2]), "=r"(br[n2][3])
                             : "r"(addr));
            }
#pragma unroll
            for (int mi = 0; mi < 4; mi++)
#pragma unroll
                for (int ni = 0; ni < 4; ni++) {
                    uint32_t b0 = br[ni >> 1][(ni & 1) * 2];
                    uint32_t b1 = br[ni >> 1][(ni & 1) * 2 + 1];
                    asm volatile(
                        "mma.sync.aligned.m16n8k16.row.col.f32.f16.f16.f32 "
                        "{%0,%1,%2,%3}, {%4,%5,%6,%7}, {%8,%9}, {%0,%1,%2,%3};"
                        : "+f"(acc[mi][ni][0]), "+f"(acc[mi][ni][1]),
                          "+f"(acc[mi][ni][2]), "+f"(acc[mi][ni][3])
                        : "r"(ar[mi][0]), "r"(ar[mi][1]), "r"(ar[mi][2]), "r"(ar[mi][3]),
                          "r"(b0), "r"(b1));
                }
        }
        __syncthreads();
    }
    f16* Cb = C + (size_t)(by * BM + wm) * N + bx * BN + wn;
#pragma unroll
    for (int mi = 0; mi < 4; mi++)
#pragma unroll
        for (int ni = 0; ni < 4; ni++) {
            int r0 = mi * 16 + (lane >> 2);
            int c0 = ni * 8 + (lane & 3) * 2;
            *(__half2*)(Cb + (size_t)r0 * N + c0)       = __floats2half2_rn(acc[mi][ni][0], acc[mi][ni][1]);
            *(__half2*)(Cb + (size_t)(r0 + 8) * N + c0) = __floats2half2_rn(acc[mi][ni][2], acc[mi][ni][3]);
        }
    // ---- fused layer-1 attention dots (warp's 32 cols lie in one head) ----
    int gcol0 = bx * BN + wn;
    int head = gcol0 >> 6;               // HID = 64
    const float* as = att_src + head * HID;
    const float* ad = att_dst + head * HID;
    int cbase = (gcol0 & 63) + (lane & 3) * 2;
#pragma unroll
    for (int mi = 0; mi < 4; mi++) {
#pragma unroll
        for (int rr = 0; rr < 2; rr++) {
            float ssum = 0.f, dsum = 0.f;
#pragma unroll
            for (int ni = 0; ni < 4; ni++) {
#pragma unroll
                for (int q = 0; q < 2; q++) {
                    int ch = cbase + ni * 8 + q;
                    float v = acc[mi][ni][rr * 2 + q];
                    ssum += v * as[ch];
                    dsum += v * ad[ch];
                }
            }
            ssum += __shfl_xor_sync(0xffffffffu, ssum, 1);
            ssum += __shfl_xor_sync(0xffffffffu, ssum, 2);
            dsum += __shfl_xor_sync(0xffffffffu, dsum, 1);
            dsum += __shfl_xor_sync(0xffffffffu, dsum, 2);
            if ((lane & 3) == 0) {
                int n = by * BM + wm + mi * 16 + (lane >> 2) + rr * 8;
                atomicAdd(&g_A1s[n * IN_HEAD + head], ssum);
                atomicAdd(&g_A1d[n * IN_HEAD + head], dsum);
            }
        }
    }
}

// ---------------- GEMM2: 4 warps, warp tile 64x64, fp32 out ----------------
__global__ __launch_bounds__(128, 2)
void hgemm2(const f16* __restrict__ A, const f16* __restrict__ B,
            float* __restrict__ Cbase, size_t cStride,
            int N, int aStride, int kLen) {
    extern __shared__ f16 smbuf[];
    f16* sA = smbuf;
    f16* sB = smbuf + STG * BM * APITCH;
    int t = threadIdx.x, lane = t & 31, warp = t >> 5;
    int wm = (warp >> 1) * 64;   // 0 or 64
    int wn = (warp & 1) * 64;    // 0 or 64
    int bx = blockIdx.x, by = blockIdx.y, bz = blockIdx.z;
    int kOff = bz * kLen;
    const f16* Ab = A + (size_t)(by * BM) * aStride + kOff;
    const f16* Bb = B + (size_t)kOff * N + bx * BN;

    float acc[4][8][4];
#pragma unroll
    for (int i = 0; i < 4; i++)
#pragma unroll
        for (int j = 0; j < 8; j++)
#pragma unroll
            for (int r = 0; r < 4; r++) acc[i][j][r] = 0.f;

    auto issue = [&](int j) {
        int buf = j % STG;
        int k0 = j * BK;
        f16* pa = sA + buf * BM * APITCH;
        f16* pb = sB + buf * BK * BPITCH;
#pragma unroll
        for (int i = 0; i < 4; i++) {          // A: 128x32 = 512 chunks of 16B
            int id = t + 128 * i;
            int row = id >> 2, c = (id & 3) * 8;
            uint32_t d = (uint32_t)__cvta_generic_to_shared(pa + row * APITCH + c);
            const f16* g = Ab + (size_t)row * aStride + k0 + c;
            asm volatile("cp.async.cg.shared.global [%0], [%1], 16;" :: "r"(d), "l"(g));
        }
#pragma unroll
        for (int i = 0; i < 4; i++) {          // B: 32x128 = 512 chunks of 16B
            int id = t + 128 * i;
            int row = id >> 4, c = (id & 15) * 8;
            uint32_t d = (uint32_t)__cvta_generic_to_shared(pb + row * BPITCH + c);
            const f16* g = Bb + (size_t)(k0 + row) * N + c;
            asm volatile("cp.async.cg.shared.global [%0], [%1], 16;" :: "r"(d), "l"(g));
        }
        asm volatile("cp.async.commit_group;");
    };

    int nc = kLen / BK;
    issue(0);
    if (nc > 1) issue(1);
    for (int s = 0; s < nc; s++) {
        if (s < nc - 1) { asm volatile("cp.async.wait_group 1;"); }
        else            { asm volatile("cp.async.wait_group 0;"); }
        __syncthreads();
        if (s + 2 < nc) issue(s + 2);
        int buf = s % STG;
        f16* pa = sA + buf * BM * APITCH;
        f16* pb = sB + buf * BK * BPITCH;
#pragma unroll
        for (int kk = 0; kk < 2; kk++) {
            int k = kk * 16;
            uint32_t ar[4][4], br[4][4];
#pragma unroll
            for (int mi = 0; mi < 4; mi++) {
                int row = wm + mi * 16 + (lane & 7) + ((lane >> 3) & 1) * 8;
                int col = k + (lane >> 4) * 8;
                uint32_t addr = (uint32_t)__cvta_generic_to_shared(pa + row * APITCH + col);
                asm volatile("ldmatrix.sync.aligned.m8n8.x4.shared.b16 {%0,%1,%2,%3}, [%4];"
                             : "=r"(ar[mi][0]), "=r"(ar[mi][1]), "=r"(ar[mi][2]), "=r"(ar[mi][3])
                             : "r"(addr));
            }
#pragma unroll
            for (int n2 = 0; n2 < 4; n2++) {
                int rrow = k + (lane & 7) + ((lane >> 3) & 1) * 8;
                int rcol = wn + n2 * 16 + (lane >> 4) * 8;
                uint32_t addr = (uint32_t)__cvta_generic_to_shared(pb + rrow * BPITCH + rcol);
                asm volatile("ldmatrix.sync.aligned.m8n8.x4.trans.shared.b16 {%0,%1,%2,%3}, [%4];"
                             : "=r"(br[n2][0]), "=r"(br[n2][1]), "=r"(br[n2][2]), "=r"(br[n2][3])
                             : "r"(addr));
            }
#pragma unroll
            for (int mi = 0; mi < 4; mi++)
#pragma unroll
                for (int ni = 0; ni < 8; ni++) {
                    uint32_t b0 = br[ni >> 1][(ni & 1) * 2];
                    uint32_t b1 = br[ni >> 1][(ni & 1) * 2 + 1];
                    asm volatile(
                        "mma.sync.aligned.m16n8k16.row.col.f32.f16.f16.f32 "
                        "{%0,%1,%2,%3}, {%4,%5,%6,%7}, {%8,%9}, {%0,%1,%2,%3};"
                        : "+f"(acc[mi][ni][0]), "+f"(acc[mi][ni][1]),
                          "+f"(acc[mi][ni][2]), "+f"(acc[mi][ni][3])
                        : "r"(ar[mi][0]), "r"(ar[mi][1]), "r"(ar[mi][2]), "r"(ar[mi][3]),
                          "r"(b0), "r"(b1));
                }
        }
        __syncthreads();
    }
    float* Cb = Cbase + bz * cStride + (size_t)(by * BM + wm) * N + bx * BN + wn;
#pragma unroll
    for (int mi = 0; mi < 4; mi++)
#pragma unroll
        for (int ni = 0; ni < 8; ni++) {
            int r0 = mi * 16 + (lane >> 2);
            int c0 = ni * 8 + (lane & 3) * 2;
            *(float2*)(Cb + (size_t)r0 * N + c0)       = make_float2(acc[mi][ni][0], acc[mi][ni][1]);
            *(float2*)(Cb + (size_t)(r0 + 8) * N + c0) = make_float2(acc[mi][ni][2], acc[mi][ni][3]);
        }
}

// ---------------- fused split-K reduce (4-way) + fp16 H2 store + layer-2 dots ----------------
__global__ void k_red_dots2(const float* __restrict__ att_src, const float* __restrict__ att_dst) {
    int n = blockIdx.x;
    int t = threadIdx.x, lane = t & 31, h = t >> 5;
    const size_t stride4 = (size_t)N_NODES * F2 / 4;
    const float4* p = (const float4*)g_Pk + (size_t)n * (F2 / 4);

    float4 v = p[t];
#pragma unroll
    for (int z = 1; z < KSPLIT; z++) {
        float4 a = p[z * stride4 + t];
        v.x += a.x; v.y += a.y; v.z += a.z; v.w += a.w;
    }
    __half2* h2 = (__half2*)g_H2h + (size_t)n * (F2 / 2);
    h2[2 * t]     = __floats2half2_rn(v.x, v.y);
    h2[2 * t + 1] = __floats2half2_rn(v.z, v.w);

    int c0 = lane * 4;
    const float* as = att_src + h * OUT_FEAT + c0;
    const float* ad = att_dst + h * OUT_FEAT + c0;
    float sa = v.x * as[0] + v.y * as[1] + v.z * as[2] + v.w * as[3];
    float sd = v.x * ad[0] + v.y * ad[1] + v.z * ad[2] + v.w * ad[3];
#pragma unroll
    for (int o = 16; o > 0; o >>= 1) {
        sa += __shfl_xor_sync(0xffffffffu, sa, o);
        sd += __shfl_xor_sync(0xffffffffu, sd, o);
    }
    if (lane == 0) {
        g_A2s[n * OUT_HEAD + h] = sa;
        g_A2d[n * OUT_HEAD + h] = sd;
    }
}

__device__ __forceinline__ float leaky(float x) { return x > 0.f ? x : NEG_SLOPE * x; }

// ---------------- Layer-1 softmax + aggregation + bias + elu -> fp16 ----------------
__global__ void k_agg1(const float* __restrict__ b1) {
    int n = blockIdx.x;
    int t = threadIdx.x;
    int h = t & 63, slot = t >> 6;
    int beg = g_offs[n], end = g_offs[n + 1];
    float adst = g_A1d[n * IN_HEAD + h];

    __shared__ float red[4][64];
    __shared__ float sm_m[64], sm_inv[64];
    __shared__ int   srcb[32];
    __shared__ float alpha[32][64];

    float mx = -1e30f;
    for (int j = beg + slot; j < end; j += 4) {
        int s = g_esrc[j];
        mx = fmaxf(mx, leaky(g_A1s[s * IN_HEAD + h] + adst));
    }
    red[slot][h] = mx;
    __syncthreads();
    if (slot == 0) {
        sm_m[h] = fmaxf(fmaxf(red[0][h], red[1][h]), fmaxf(red[2][h], red[3][h]));
    }
    __syncthreads();
    float M = sm_m[h];

    float sum = 0.f;
    for (int j = beg + slot; j < end; j += 4) {
        int s = g_esrc[j];
        sum += expf(leaky(g_A1s[s * IN_HEAD + h] + adst) - M);
    }
    red[slot][h] = sum;
    __syncthreads();
    if (slot == 0) {
        float d = red[0][h] + red[1][h] + red[2][h] + red[3][h];
        sm_inv[h] = 1.0f / (d + GAT_EPS);
    }
    __syncthreads();
    float INV = sm_inv[h];

    int c2 = t & 31, g = t >> 5;   // half2 pair, head group of 8
    float2 acc[8];
#pragma unroll
    for (int k = 0; k < 8; k++) acc[k] = make_float2(0.f, 0.f);

    for (int jb = beg; jb < end; jb += 32) {
        int cnt = min(32, end - jb);
        if (t < cnt) srcb[t] = g_esrc[jb + t];
        __syncthreads();
        for (int j = slot; j < cnt; j += 4) {
            int s = srcb[j];
            float e = leaky(g_A1s[s * IN_HEAD + h] + adst);
            alpha[j][h] = expf(e - M) * INV;
        }
        __syncthreads();
        int j = 0;
        for (; j + 3 < cnt; j += 4) {
            const __half2* r0 = (const __half2*)(g_H1h + (size_t)srcb[j] * F1);
            const __half2* r1 = (const __half2*)(g_H1h + (size_t)srcb[j + 1] * F1);
            const __half2* r2 = (const __half2*)(g_H1h + (size_t)srcb[j + 2] * F1);
            const __half2* r3 = (const __half2*)(g_H1h + (size_t)srcb[j + 3] * F1);
#pragma unroll
            for (int k = 0; k < 8; k++) {
                int hh = g * 8 + k;
                int idx = hh * 32 + c2;
                float2 f0 = __half22float2(r0[idx]);
                float2 f1 = __half22float2(r1[idx]);
                float2 f2 = __half22float2(r2[idx]);
                float2 f3 = __half22float2(r3[idx]);
                float a0 = alpha[j][hh], a1 = alpha[j + 1][hh];
                float a2 = alpha[j + 2][hh], a3 = alpha[j + 3][hh];
                acc[k].x += a0 * f0.x + a1 * f1.x + a2 * f2.x + a3 * f3.x;
                acc[k].y += a0 * f0.y + a1 * f1.y + a2 * f2.y + a3 * f3.y;
            }
        }
        for (; j < cnt; j++) {
            const __half2* row = (const __half2*)(g_H1h + (size_t)srcb[j] * F1);
#pragma unroll
            for (int k = 0; k < 8; k++) {
                int hh = g * 8 + k;
                float2 f = __half22float2(row[hh * 32 + c2]);
                float a = alpha[j][hh];
                acc[k].x += a * f.x;
                acc[k].y += a * f.y;
            }
        }
        __syncthreads();
    }
    __half2* rowo = (__half2*)(g_H1ae + (size_t)n * F1);
#pragma unroll
    for (int k = 0; k < 8; k++) {
        int hh = g * 8 + k;
        float vx = acc[k].x + b1[hh * HID + 2 * c2];
        float vy = acc[k].y + b1[hh * HID + 2 * c2 + 1];
        vx = vx > 0.f ? vx : expm1f(vx);
        vy = vy > 0.f ? vy : expm1f(vy);
        rowo[hh * 32 + c2] = __floats2half2_rn(vx, vy);
    }
}

// ---------------- Layer-2 softmax + aggregation + head-mean + bias + fused node-sum ----------------
__global__ void k_agg2(const float* __restrict__ b2) {
    int n = blockIdx.x;
    int t = threadIdx.x;
    int beg = g_offs[n], end = g_offs[n + 1];

    __shared__ float sm_m[OUT_HEAD], sm_inv[OUT_HEAD];
    __shared__ int   srcb[16];
    __shared__ float alpha[16][OUT_HEAD];

    if (t < OUT_HEAD) {
        float adst = g_A2d[n * OUT_HEAD + t];
        float mx = -1e30f;
        for (int j = beg; j < end; j++)
            mx = fmaxf(mx, leaky(g_A2s[g_esrc[j] * OUT_HEAD + t] + adst));
        float sum = 0.f;
        for (int j = beg; j < end; j++)
            sum += expf(leaky(g_A2s[g_esrc[j] * OUT_HEAD + t] + adst) - mx);
        sm_m[t] = mx;
        sm_inv[t] = 1.0f / (sum + GAT_EPS);
    }
    __syncthreads();

    float acc[OUT_HEAD] = {0.f, 0.f, 0.f, 0.f, 0.f};
    for (int jb = beg; jb < end; jb += 16) {
        int cnt = min(16, end - jb);
        if (t < cnt) srcb[t] = g_esrc[jb + t];
        __syncthreads();
        if (t < cnt * OUT_HEAD) {
            int j = t / OUT_HEAD, hh = t % OUT_HEAD;
            int s = srcb[j];
            float e = leaky(g_A2s[s * OUT_HEAD + hh] + g_A2d[n * OUT_HEAD + hh]);
            alpha[j][hh] = expf(e - sm_m[hh]) * sm_inv[hh];
        }
        __syncthreads();
        for (int j = 0; j < cnt; j++) {
            const f16* row = g_H2h + (size_t)srcb[j] * F2;
#pragma unroll
            for (int hh = 0; hh < OUT_HEAD; hh++)
                acc[hh] += alpha[j][hh] * __half2float(row[hh * OUT_FEAT + t]);
        }
        __syncthreads();
    }
    float o = (acc[0] + acc[1] + acc[2] + acc[3] + acc[4]) * 0.2f + b2[t];
    atomicAdd(&g_part[(n & 31) * OUT_FEAT + t], o);
}

// ---------------- Final node-mean + tanh ----------------
__global__ void k_final(float* __restrict__ out) {
    int c = threadIdx.x;
    float s = 0.f;
#pragma unroll
    for (int b = 0; b < 32; b++) s += g_part[b * OUT_FEAT + c];
    out[c] = tanhf(s / (float)N_NODES);
}

// ---------------- Launch ----------------
extern "C" void kernel_launch(void* const* d_in, const int* in_sizes, int n_in,
                              void* d_out, int out_size) {
    const float* x        = (const float*)d_in[0];
    const void*  ei       = d_in[1];
    const float* W1       = (const float*)d_in[2];
    const float* att_src1 = (const float*)d_in[3];
    const float* att_dst1 = (const float*)d_in[4];
    const float* b1       = (const float*)d_in[5];
    const float* W2       = (const float*)d_in[6];
    const float* att_src2 = (const float*)d_in[7];
    const float* att_dst2 = (const float*)d_in[8];
    const float* b2       = (const float*)d_in[9];
    float* out = (float*)d_out;

    static f16*   s_H1h  = nullptr;
    static float* s_Pk   = nullptr;
    static f16*   s_xh   = nullptr;
    static f16*   s_W1h  = nullptr;
    static f16*   s_H1ae = nullptr;
    static f16*   s_W2h  = nullptr;
    static cudaStream_t s2 = nullptr;
    static cudaEvent_t  evFork = nullptr, evJoin = nullptr;
    static bool   s_init = false;
    if (!s_init) {
        cudaGetSymbolAddress((void**)&s_H1h,  g_H1h);
        cudaGetSymbolAddress((void**)&s_Pk,   g_Pk);
        cudaGetSymbolAddress((void**)&s_xh,   g_xh);
        cudaGetSymbolAddress((void**)&s_W1h,  g_W1h);
        cudaGetSymbolAddress((void**)&s_H1ae, g_H1ae);
        cudaGetSymbolAddress((void**)&s_W2h,  g_W2h);
        cudaFuncSetAttribute(hgemm1, cudaFuncAttributeMaxDynamicSharedMemorySize, HG_SMEM);
        cudaFuncSetAttribute(hgemm2, cudaFuncAttributeMaxDynamicSharedMemorySize, HG_SMEM);
        cudaStreamCreateWithFlags(&s2, cudaStreamNonBlocking);
        cudaEventCreateWithFlags(&evFork, cudaEventDisableTiming);
        cudaEventCreateWithFlags(&evJoin, cudaEventDisableTiming);
        s_init = true;
    }

    // ---- fork: CSR chain + W2 convert on s2, concurrent with GEMM1 path ----
    cudaEventRecord(evFork, 0);
    cudaStreamWaitEvent(s2, evFork, 0);

    k_init   <<<(N_NODES + 256) / 256, 256, 0, s2>>>((const int*)ei);
    k_count  <<<(E2 + 255) / 256, 256, 0, s2>>>(ei);
    k_scan   <<<1, 1024, 0, s2>>>();
    k_scatter<<<(E2 + 255) / 256, 256, 0, s2>>>(ei);
    k_cvt_W2 <<<((F1 * F2 / 4) + 255) / 256, 256, 0, s2>>>(W2);
    cudaEventRecord(evJoin, s2);

    // ---- main stream: GEMM1 path (k_cvt_x zeroes A1s/A1d/g_part) ----
    k_cvt_x <<<(N_NODES * IN_FEAT / 4) / 256, 256>>>(x);
    k_cvt_W1<<<(IN_FEAT * F1 / 4) / 256, 256>>>(W1);

    // GEMM1: H1h = x_f16 @ W1_f16, K=256, fp16 out + fused layer-1 dots
    hgemm1<<<dim3(F1 / BN, N_NODES / BM), 256, HG_SMEM>>>(
        s_xh, s_W1h, s_H1h, F1, IN_FEAT, IN_FEAT, att_src1, att_dst1);

    // ---- join: agg1 needs CSR; GEMM2 needs W2h ----
    cudaStreamWaitEvent(0, evJoin, 0);

    k_agg1<<<N_NODES, 256>>>(b1);

    // GEMM2: 64x64 warp tiles, split-K=4, kLen=1024 (640 CTAs)
    hgemm2<<<dim3(F2 / BN, N_NODES / BM, KSPLIT), 128, HG_SMEM>>>(
        s_H1ae, s_W2h, s_Pk, (size_t)N_NODES * F2, F2, F1, F1 / KSPLIT);

    // fused: H2h = sum(Pk) (fp16) + layer-2 attention dots
    k_red_dots2<<<N_NODES, 160>>>(att_src2, att_dst2);

    // agg2 with fused partial node-sum (atomicAdd into g_part)
    k_agg2<<<N_NODES, 128>>>(b2);

    k_final<<<1, 128>>>(out);
}

// round 16
// speedup vs baseline: 1.6395x; 1.0042x over previous
#include <cuda_runtime.h>
#include <cuda_fp16.h>
#include <stdint.h>
#include <math.h>

typedef __half f16;

// ---------------- Problem constants ----------------
#define N_NODES 4096
#define N_EDGES 32768
#define E2      (N_EDGES + N_NODES)   // with self loops = 36864
#define IN_FEAT 256
#define HID     64
#define IN_HEAD 64
#define OUT_FEAT 128
#define OUT_HEAD 5
#define F1      (IN_HEAD * HID)       // 4096
#define F2      (OUT_HEAD * OUT_FEAT) // 640
#define NEG_SLOPE 0.2f
#define GAT_EPS 1e-16f
#define KSPLIT  4

// ---------------- Device scratch ----------------
__device__ int   g_is64;
__device__ int   g_counts[N_NODES + 1];
__device__ int   g_offs[N_NODES + 1];
__device__ int   g_cursor[N_NODES];
__device__ int   g_esrc[E2];
__device__ f16   g_H1h[(size_t)N_NODES * F1];     // x @ W1 in fp16 (32 MB)
__device__ float g_A1s[(size_t)N_NODES * IN_HEAD];
__device__ float g_A1d[(size_t)N_NODES * IN_HEAD];
__device__ float g_Pk [(size_t)KSPLIT * N_NODES * F2];  // split-K partials (40 MB)
__device__ f16   g_H2h[(size_t)N_NODES * F2];     // H1a @ W2 in fp16 (5 MB)
__device__ float g_A2s[(size_t)N_NODES * OUT_HEAD];
__device__ float g_A2d[(size_t)N_NODES * OUT_HEAD];
__device__ float g_part[32 * OUT_FEAT];

// fp16 operands
__device__ f16   g_xh  [(size_t)N_NODES * IN_FEAT]; // 2 MB
__device__ f16   g_W1h [(size_t)IN_FEAT * F1];      // 2 MB
__device__ f16   g_H1ae[(size_t)N_NODES * F1];      // 32 MB (elu(agg1+b1) fp16)
__device__ f16   g_W2h [(size_t)F1 * F2];           // 5.2 MB

// ---------------- init: zero counts + int64/int32 detect ----------------
__global__ void k_init(const int* ei32) {
    int i = blockIdx.x * blockDim.x + threadIdx.x;
    if (i <= N_NODES) g_counts[i] = 0;
    if (blockIdx.x == 0 && threadIdx.x < 32) {
        int v = ei32[2 * threadIdx.x + 1];
        unsigned any = __ballot_sync(0xffffffffu, v != 0);
        if (threadIdx.x == 0) g_is64 = (any == 0) ? 1 : 0;
    }
}

__device__ __forceinline__ int load_ei(const void* ei, int idx) {
    if (g_is64) return (int)((const long long*)ei)[idx];
    return ((const int*)ei)[idx];
}

// ---------------- CSR build ----------------
__global__ void k_count(const void* ei) {
    int i = blockIdx.x * blockDim.x + threadIdx.x;
    if (i >= E2) return;
    int dst = (i < N_EDGES) ? load_ei(ei, N_EDGES + i) : (i - N_EDGES);
    atomicAdd(&g_counts[dst], 1);
}

__global__ void k_scan() {   // 1 block, 1024 threads; scan 4096 counts
    __shared__ int buf[2][1024];
    int t = threadIdx.x;
    int c0 = g_counts[4 * t], c1 = g_counts[4 * t + 1];
    int c2 = g_counts[4 * t + 2], c3 = g_counts[4 * t + 3];
    int s = c0 + c1 + c2 + c3;
    buf[0][t] = s;
    __syncthreads();
    int pin = 0;
    for (int off = 1; off < 1024; off <<= 1) {
        int v = buf[pin][t];
        if (t >= off) v += buf[pin][t - off];
        buf[pin ^ 1][t] = v;
        pin ^= 1;
        __syncthreads();
    }
    int incl = buf[pin][t];
    int base = incl - s;
    g_offs[4 * t]     = base;
    g_offs[4 * t + 1] = base + c0;
    g_offs[4 * t + 2] = base + c0 + c1;
    g_offs[4 * t + 3] = base + c0 + c1 + c2;
    g_cursor[4 * t]     = base;
    g_cursor[4 * t + 1] = base + c0;
    g_cursor[4 * t + 2] = base + c0 + c1;
    g_cursor[4 * t + 3] = base + c0 + c1 + c2;
    if (t == 1023) g_offs[N_NODES] = incl;
}

__global__ void k_scatter(const void* ei) {
    int i = blockIdx.x * blockDim.x + threadIdx.x;
    if (i >= E2) return;
    int src, dst;
    if (i < N_EDGES) { src = load_ei(ei, i); dst = load_ei(ei, N_EDGES + i); }
    else             { src = i - N_EDGES;    dst = i - N_EDGES; }
    int pos = atomicAdd(&g_cursor[dst], 1);
    g_esrc[pos] = src;
}

// ---------------- fp16 convert kernels (vectorized) ----------------
// Merged x + W1 convert; also zero-inits A1s/A1d and g_part each replay.
// Grid: 2048 blocks x 256; first 1024 blocks handle x, rest handle W1.
__global__ void k_cvt_xw1(const float* __restrict__ x, const float* __restrict__ W1) {
    int i = blockIdx.x * blockDim.x + threadIdx.x;   // 524288 threads
    const int NX = N_NODES * IN_FEAT / 4;            // 262144 float4s
    if (i < NX) {
        float4 v = ((const float4*)x)[i];
        __half2* o = (__half2*)g_xh;
        o[2 * i]     = __floats2half2_rn(v.x, v.y);
        o[2 * i + 1] = __floats2half2_rn(v.z, v.w);
        g_A1s[i] = 0.f;                              // N_NODES*IN_HEAD == 262144
        g_A1d[i] = 0.f;
        if (i < 32 * OUT_FEAT) g_part[i] = 0.f;
    } else {
        int j = i - NX;                              // 262144 float4s of W1
        float4 v = ((const float4*)W1)[j];
        __half2* o = (__half2*)g_W1h;
        o[2 * j]     = __floats2half2_rn(v.x, v.y);
        o[2 * j + 1] = __floats2half2_rn(v.z, v.w);
    }
}

__global__ void k_cvt_W2(const float* __restrict__ W) {
    int i = blockIdx.x * blockDim.x + threadIdx.x;
    if (i >= (F1 * F2) / 4) return;
    float4 v = ((const float4*)W)[i];
    __half2* o = (__half2*)g_W2h;
    o[2 * i]     = __floats2half2_rn(v.x, v.y);
    o[2 * i + 1] = __floats2half2_rn(v.z, v.w);
}

// ---------------- shared GEMM geometry ----------------
#define BM 128
#define BN 128
#define BK 32
#define STG 3
#define APITCH (BK + 8)
#define BPITCH (BN + 8)
#define HG_SMEM (STG * (BM * APITCH + BK * BPITCH) * 2)

// GEMM2 geometry (BK = 64)
#define BK2 64
#define APITCH2 (BK2 + 8)          // 72
#define HG2_SMEM (STG * (BM * APITCH2 + BK2 * BPITCH) * 2)   // 107520 B

// ---------------- GEMM1: 8 warps, warp tile 64x32, fp16 out + fused dots1 ----------------
__global__ __launch_bounds__(256, 2)
void hgemm1(const f16* __restrict__ A, const f16* __restrict__ B,
            f16* __restrict__ C, int N, int aStride, int kLen,
            const float* __restrict__ att_src, const float* __restrict__ att_dst) {
    extern __shared__ f16 smbuf[];
    f16* sA = smbuf;
    f16* sB = smbuf + STG * BM * APITCH;
    int t = threadIdx.x, lane = t & 31, warp = t >> 5;
    int wm = (warp >> 2) * 64;
    int wn = (warp & 3) * 32;
    int bx = blockIdx.x, by = blockIdx.y;
    const f16* Ab = A + (size_t)(by * BM) * aStride;
    const f16* Bb = B + bx * BN;

    int a_row = t >> 2;
    int a_col = (t & 3) * 8;
    int b_row = t >> 4;
    int b_col = (t & 15) * 8;

    float acc[4][4][4];
#pragma unroll
    for (int i = 0; i < 4; i++)
#pragma unroll
        for (int j = 0; j < 4; j++)
#pragma unroll
            for (int r = 0; r < 4; r++) acc[i][j][r] = 0.f;

    auto issue = [&](int j) {
        int buf = j % STG;
        int k0 = j * BK;
        f16* pa = sA + buf * BM * APITCH;
        f16* pb = sB + buf * BK * BPITCH;
        uint32_t da0 = (uint32_t)__cvta_generic_to_shared(pa + a_row * APITCH + a_col);
        uint32_t da1 = (uint32_t)__cvta_generic_to_shared(pa + (a_row + 64) * APITCH + a_col);
        const f16* ga0 = Ab + (size_t)a_row * aStride + k0 + a_col;
        const f16* ga1 = Ab + (size_t)(a_row + 64) * aStride + k0 + a_col;
        asm volatile("cp.async.cg.shared.global [%0], [%1], 16;" :: "r"(da0), "l"(ga0));
        asm volatile("cp.async.cg.shared.global [%0], [%1], 16;" :: "r"(da1), "l"(ga1));
        uint32_t db0 = (uint32_t)__cvta_generic_to_shared(pb + b_row * BPITCH + b_col);
        uint32_t db1 = (uint32_t)__cvta_generic_to_shared(pb + (b_row + 16) * BPITCH + b_col);
        const f16* gb0 = Bb + (size_t)(k0 + b_row) * N + b_col;
        const f16* gb1 = Bb + (size_t)(k0 + b_row + 16) * N + b_col;
        asm volatile("cp.async.cg.shared.global [%0], [%1], 16;" :: "r"(db0), "l"(gb0));
        asm volatile("cp.async.cg.shared.global [%0], [%1], 16;" :: "r"(db1), "l"(gb1));
        asm volatile("cp.async.commit_group;");
    };

    int nc = kLen / BK;
    issue(0);
    if (nc > 1) issue(1);
    for (int s = 0; s < nc; s++) {
        if (s < nc - 1) { asm volatile("cp.async.wait_group 1;"); }
        else            { asm volatile("cp.async.wait_group 0;"); }
        __syncthreads();
        if (s + 2 < nc) issue(s + 2);
        int buf = s % STG;
        f16* pa = sA + buf * BM * APITCH;
        f16* pb = sB + buf * BK * BPITCH;
#pragma unroll
        for (int kk = 0; kk < 2; kk++) {
            int k = kk * 16;
            uint32_t ar[4][4], br[2][4];
#pragma unroll
            for (int mi = 0; mi < 4; mi++) {
                int row = wm + mi * 16 + (lane & 7) + ((lane >> 3) & 1) * 8;
                int col = k + (lane >> 4) * 8;
                uint32_t addr = (uint32_t)__cvta_generic_to_shared(pa + row * APITCH + col);
                asm volatile("ldmatrix.sync.aligned.m8n8.x4.shared.b16 {%0,%1,%2,%3}, [%4];"
                             : "=r"(ar[mi][0]), "=r"(ar[mi][1]), "=r"(ar[mi][2]), "=r"(ar[mi][3])
                             : "r"(addr));
            }
#pragma unroll
            for (int n2 = 0; n2 < 2; n2++) {
                int rrow = k + (lane & 7) + ((lane >> 3) & 1) * 8;
                int rcol = wn + n2 * 16 + (lane >> 4) * 8;
                uint32_t addr = (uint32_t)__cvta_generic_to_shared(pb + rrow * BPITCH + rcol);
                asm volatile("ldmatrix.sync.aligned.m8n8.x4.trans.shared.b16 {%0,%1,%2,%3}, [%4];"
                             : "=r"(br[n2][0]), "=r"(br[n2][1]), "=r"(br[n2][2]), "=r"(br[n2][3])
                             : "r"(addr));
            }
#pragma unroll
            for (int mi = 0; mi < 4; mi++)
#pragma unroll
                for (int ni = 0; ni < 4; ni++) {
                    uint32_t b0 = br[ni >> 1][(ni & 1) * 2];
                    uint32_t b1 = br[ni >> 1][(ni & 1) * 2 + 1];
                    asm volatile(
                        "mma.sync.aligned.m16n8k16.row.col.f32.f16.f16.f32 "
                        "{%0,%1,%2,%3}, {%4,%5,%6,%7}, {%8,%9}, {%0,%1,%2,%3};"
                        : "+f"(acc[mi][ni][0]), "+f"(acc[mi][ni][1]),
                          "+f"(acc[mi][ni][2]), "+f"(acc[mi][ni][3])
                        : "r"(ar[mi][0]), "r"(ar[mi][1]), "r"(ar[mi][2]), "r"(ar[mi][3]),
                          "r"(b0), "r"(b1));
                }
        }
        __syncthreads();
    }
    f16* Cb = C + (size_t)(by * BM + wm) * N + bx * BN + wn;
#pragma unroll
    for (int mi = 0; mi < 4; mi++)
#pragma unroll
        for (int ni = 0; ni < 4; ni++) {
            int r0 = mi * 16 + (lane >> 2);
            int c0 = ni * 8 + (lane & 3) * 2;
            *(__half2*)(Cb + (size_t)r0 * N + c0)       = __floats2half2_rn(acc[mi][ni][0], acc[mi][ni][1]);
            *(__half2*)(Cb + (size_t)(r0 + 8) * N + c0) = __floats2half2_rn(acc[mi][ni][2], acc[mi][ni][3]);
        }
    // ---- fused layer-1 attention dots (warp's 32 cols lie in one head) ----
    int gcol0 = bx * BN + wn;
    int head = gcol0 >> 6;               // HID = 64
    const float* as = att_src + head * HID;
    const float* ad = att_dst + head * HID;
    int cbase = (gcol0 & 63) + (lane & 3) * 2;
#pragma unroll
    for (int mi = 0; mi < 4; mi++) {
#pragma unroll
        for (int rr = 0; rr < 2; rr++) {
            float ssum = 0.f, dsum = 0.f;
#pragma unroll
            for (int ni = 0; ni < 4; ni++) {
#pragma unroll
                for (int q = 0; q < 2; q++) {
                    int ch = cbase + ni * 8 + q;
                    float v = acc[mi][ni][rr * 2 + q];
                    ssum += v * as[ch];
                    dsum += v * ad[ch];
                }
            }
            ssum += __shfl_xor_sync(0xffffffffu, ssum, 1);
            ssum += __shfl_xor_sync(0xffffffffu, ssum, 2);
            dsum += __shfl_xor_sync(0xffffffffu, dsum, 1);
            dsum += __shfl_xor_sync(0xffffffffu, dsum, 2);
            if ((lane & 3) == 0) {
                int n = by * BM + wm + mi * 16 + (lane >> 2) + rr * 8;
                atomicAdd(&g_A1s[n * IN_HEAD + head], ssum);
                atomicAdd(&g_A1d[n * IN_HEAD + head], dsum);
            }
        }
    }
}

// ---------------- GEMM2: 4 warps, warp tile 64x64, BK=64, fp32 out ----------------
__global__ __launch_bounds__(128, 2)
void hgemm2(const f16* __restrict__ A, const f16* __restrict__ B,
            float* __restrict__ Cbase, size_t cStride,
            int N, int aStride, int kLen) {
    extern __shared__ f16 smbuf[];
    f16* sA = smbuf;                               // [STG][128][APITCH2]
    f16* sB = smbuf + STG * BM * APITCH2;          // [STG][64][BPITCH]
    int t = threadIdx.x, lane = t & 31, warp = t >> 5;
    int wm = (warp >> 1) * 64;   // 0 or 64
    int wn = (warp & 1) * 64;    // 0 or 64
    int bx = blockIdx.x, by = blockIdx.y, bz = blockIdx.z;
    int kOff = bz * kLen;
    const f16* Ab = A + (size_t)(by * BM) * aStride + kOff;
    const f16* Bb = B + (size_t)kOff * N + bx * BN;

    float acc[4][8][4];
#pragma unroll
    for (int i = 0; i < 4; i++)
#pragma unroll
        for (int j = 0; j < 8; j++)
#pragma unroll
            for (int r = 0; r < 4; r++) acc[i][j][r] = 0.f;

    auto issue = [&](int j) {
        int buf = j % STG;
        int k0 = j * BK2;
        f16* pa = sA + buf * BM * APITCH2;
        f16* pb = sB + buf * BK2 * BPITCH;
#pragma unroll
        for (int i = 0; i < 8; i++) {          // A: 128x64 = 1024 chunks of 16B
            int id = t + 128 * i;
            int row = id >> 3, c = (id & 7) * 8;
            uint32_t d = (uint32_t)__cvta_generic_to_shared(pa + row * APITCH2 + c);
            const f16* g = Ab + (size_t)row * aStride + k0 + c;
            asm volatile("cp.async.cg.shared.global [%0], [%1], 16;" :: "r"(d), "l"(g));
        }
#pragma unroll
        for (int i = 0; i < 8; i++) {          // B: 64x128 = 1024 chunks of 16B
            int id = t + 128 * i;
            int row = id >> 4, c = (id & 15) * 8;
            uint32_t d = (uint32_t)__cvta_generic_to_shared(pb + row * BPITCH + c);
            const f16* g = Bb + (size_t)(k0 + row) * N + c;
            asm volatile("cp.async.cg.shared.global [%0], [%1], 16;" :: "r"(d), "l"(g));
        }
        asm volatile("cp.async.commit_group;");
    };

    int nc = kLen / BK2;
    issue(0);
    if (nc > 1) issue(1);
    for (int s = 0; s < nc; s++) {
        if (s < nc - 1) { asm volatile("cp.async.wait_group 1;"); }
        else            { asm volatile("cp.async.wait_group 0;"); }
        __syncthreads();
        if (s + 2 < nc) issue(s + 2);
        int buf = s % STG;
        f16* pa = sA + buf * BM * APITCH2;
        f16* pb = sB + buf * BK2 * BPITCH;
#pragma unroll
        for (int kk = 0; kk < 4; kk++) {
            int k = kk * 16;
            uint32_t ar[4][4], br[4][4];
#pragma unroll
            for (int mi = 0; mi < 4; mi++) {
                int row = wm + mi * 16 + (lane & 7) + ((lane >> 3) & 1) * 8;
                int col = k + (lane >> 4) * 8;
                uint32_t addr = (uint32_t)__cvta_generic_to_shared(pa + row * APITCH2 + col);
                asm volatile("ldmatrix.sync.aligned.m8n8.x4.shared.b16 {%0,%1,%2,%3}, [%4];"
                             : "=r"(ar[mi][0]), "=r"(ar[mi][1]), "=r"(ar[mi][2]), "=r"(ar[mi][3])
                             : "r"(addr));
            }
#pragma unroll
            for (int n2 = 0; n2 < 4; n2++) {
                int rrow = k + (lane & 7) + ((lane >> 3) & 1) * 8;
                int rcol = wn + n2 * 16 + (lane >> 4) * 8;
                uint32_t addr = (uint32_t)__cvta_generic_to_shared(pb + rrow * BPITCH + rcol);
                asm volatile("ldmatrix.sync.aligned.m8n8.x4.trans.shared.b16 {%0,%1,%2,%3}, [%4];"
                             : "=r"(br[n2][0]), "=r"(br[n2][1]), "=r"(br[n2][2]), "=r"(br[n2][3])
                             : "r"(addr));
            }
#pragma unroll
            for (int mi = 0; mi < 4; mi++)
#pragma unroll
                for (int ni = 0; ni < 8; ni++) {
                    uint32_t b0 = br[ni >> 1][(ni & 1) * 2];
                    uint32_t b1 = br[ni >> 1][(ni & 1) * 2 + 1];
                    asm volatile(
                        "mma.sync.aligned.m16n8k16.row.col.f32.f16.f16.f32 "
                        "{%0,%1,%2,%3}, {%4,%5,%6,%7}, {%8,%9}, {%0,%1,%2,%3};"
                        : "+f"(acc[mi][ni][0]), "+f"(acc[mi][ni][1]),
                          "+f"(acc[mi][ni][2]), "+f"(acc[mi][ni][3])
                        : "r"(ar[mi][0]), "r"(ar[mi][1]), "r"(ar[mi][2]), "r"(ar[mi][3]),
                          "r"(b0), "r"(b1));
                }
        }
        __syncthreads();
    }
    float* Cb = Cbase + bz * cStride + (size_t)(by * BM + wm) * N + bx * BN + wn;
#pragma unroll
    for (int mi = 0; mi < 4; mi++)
#pragma unroll
        for (int ni = 0; ni < 8; ni++) {
            int r0 = mi * 16 + (lane >> 2);
            int c0 = ni * 8 + (lane & 3) * 2;
            *(float2*)(Cb + (size_t)r0 * N + c0)       = make_float2(acc[mi][ni][0], acc[mi][ni][1]);
            *(float2*)(Cb + (size_t)(r0 + 8) * N + c0) = make_float2(acc[mi][ni][2], acc[mi][ni][3]);
        }
}

// ---------------- fused split-K reduce (4-way) + fp16 H2 store + layer-2 dots ----------------
__global__ void k_red_dots2(const float* __restrict__ att_src, const float* __restrict__ att_dst) {
    int n = blockIdx.x;
    int t = threadIdx.x, lane = t & 31, h = t >> 5;
    const size_t stride4 = (size_t)N_NODES * F2 / 4;
    const float4* p = (const float4*)g_Pk + (size_t)n * (F2 / 4);

    float4 v = p[t];
#pragma unroll
    for (int z = 1; z < KSPLIT; z++) {
        float4 a = p[z * stride4 + t];
        v.x += a.x; v.y += a.y; v.z += a.z; v.w += a.w;
    }
    __half2* h2 = (__half2*)g_H2h + (size_t)n * (F2 / 2);
    h2[2 * t]     = __floats2half2_rn(v.x, v.y);
    h2[2 * t + 1] = __floats2half2_rn(v.z, v.w);

    int c0 = lane * 4;
    const float* as = att_src + h * OUT_FEAT + c0;
    const float* ad = att_dst + h * OUT_FEAT + c0;
    float sa = v.x * as[0] + v.y * as[1] + v.z * as[2] + v.w * as[3];
    float sd = v.x * ad[0] + v.y * ad[1] + v.z * ad[2] + v.w * ad[3];
#pragma unroll
    for (int o = 16; o > 0; o >>= 1) {
        sa += __shfl_xor_sync(0xffffffffu, sa, o);
        sd += __shfl_xor_sync(0xffffffffu, sd, o);
    }
    if (lane == 0) {
        g_A2s[n * OUT_HEAD + h] = sa;
        g_A2d[n * OUT_HEAD + h] = sd;
    }
}

__device__ __forceinline__ float leaky(float x) { return x > 0.f ? x : NEG_SLOPE * x; }

// ---------------- Layer-1 softmax + aggregation + bias + elu -> fp16 ----------------
__global__ void k_agg1(const float* __restrict__ b1) {
    int n = blockIdx.x;
    int t = threadIdx.x;
    int h = t & 63, slot = t >> 6;
    int beg = g_offs[n], end = g_offs[n + 1];
    float adst = g_A1d[n * IN_HEAD + h];

    __shared__ float red[4][64];
    __shared__ float sm_m[64], sm_inv[64];
    __shared__ int   srcb[32];
    __shared__ float alpha[32][64];

    float mx = -1e30f;
    for (int j = beg + slot; j < end; j += 4) {
        int s = g_esrc[j];
        mx = fmaxf(mx, leaky(g_A1s[s * IN_HEAD + h] + adst));
    }
    red[slot][h] = mx;
    __syncthreads();
    if (slot == 0) {
        sm_m[h] = fmaxf(fmaxf(red[0][h], red[1][h]), fmaxf(red[2][h], red[3][h]));
    }
    __syncthreads();
    float M = sm_m[h];

    float sum = 0.f;
    for (int j = beg + slot; j < end; j += 4) {
        int s = g_esrc[j];
        sum += expf(leaky(g_A1s[s * IN_HEAD + h] + adst) - M);
    }
    red[slot][h] = sum;
    __syncthreads();
    if (slot == 0) {
        float d = red[0][h] + red[1][h] + red[2][h] + red[3][h];
        sm_inv[h] = 1.0f / (d + GAT_EPS);
    }
    __syncthreads();
    float INV = sm_inv[h];

    int c2 = t & 31, g = t >> 5;   // half2 pair, head group of 8
    float2 acc[8];
#pragma unroll
    for (int k = 0; k < 8; k++) acc[k] = make_float2(0.f, 0.f);

    for (int jb = beg; jb < end; jb += 32) {
        int cnt = min(32, end - jb);
        if (t < cnt) srcb[t] = g_esrc[jb + t];
        __syncthreads();
        for (int j = slot; j < cnt; j += 4) {
            int s = srcb[j];
            float e = leaky(g_A1s[s * IN_HEAD + h] + adst);
            alpha[j][h] = expf(e - M) * INV;
        }
        __syncthreads();
        int j = 0;
        for (; j + 3 < cnt; j += 4) {
            const __half2* r0 = (const __half2*)(g_H1h + (size_t)srcb[j] * F1);
            const __half2* r1 = (const __half2*)(g_H1h + (size_t)srcb[j + 1] * F1);
            const __half2* r2 = (const __half2*)(g_H1h + (size_t)srcb[j + 2] * F1);
            const __half2* r3 = (const __half2*)(g_H1h + (size_t)srcb[j + 3] * F1);
#pragma unroll
            for (int k = 0; k < 8; k++) {
                int hh = g * 8 + k;
                int idx = hh * 32 + c2;
                float2 f0 = __half22float2(r0[idx]);
                float2 f1 = __half22float2(r1[idx]);
                float2 f2 = __half22float2(r2[idx]);
                float2 f3 = __half22float2(r3[idx]);
                float a0 = alpha[j][hh], a1 = alpha[j + 1][hh];
                float a2 = alpha[j + 2][hh], a3 = alpha[j + 3][hh];
                acc[k].x += a0 * f0.x + a1 * f1.x + a2 * f2.x + a3 * f3.x;
                acc[k].y += a0 * f0.y + a1 * f1.y + a2 * f2.y + a3 * f3.y;
            }
        }
        for (; j < cnt; j++) {
            const __half2* row = (const __half2*)(g_H1h + (size_t)srcb[j] * F1);
#pragma unroll
            for (int k = 0; k < 8; k++) {
                int hh = g * 8 + k;
                float2 f = __half22float2(row[hh * 32 + c2]);
                float a = alpha[j][hh];
                acc[k].x += a * f.x;
                acc[k].y += a * f.y;
            }
        }
        __syncthreads();
    }
    __half2* rowo = (__half2*)(g_H1ae + (size_t)n * F1);
#pragma unroll
    for (int k = 0; k < 8; k++) {
        int hh = g * 8 + k;
        float vx = acc[k].x + b1[hh * HID + 2 * c2];
        float vy = acc[k].y + b1[hh * HID + 2 * c2 + 1];
        vx = vx > 0.f ? vx : expm1f(vx);
        vy = vy > 0.f ? vy : expm1f(vy);
        rowo[hh * 32 + c2] = __floats2half2_rn(vx, vy);
    }
}

// ---------------- Layer-2 softmax + aggregation + head-mean + bias + fused node-sum ----------------
__global__ void k_agg2(const float* __restrict__ b2) {
    int n = blockIdx.x;
    int t = threadIdx.x;
    int beg = g_offs[n], end = g_offs[n + 1];

    __shared__ float sm_m[OUT_HEAD], sm_inv[OUT_HEAD];
    __shared__ int   srcb[16];
    __shared__ float alpha[16][OUT_HEAD];

    if (t < OUT_HEAD) {
        float adst = g_A2d[n * OUT_HEAD + t];
        float mx = -1e30f;
        for (int j = beg; j < end; j++)
            mx = fmaxf(mx, leaky(g_A2s[g_esrc[j] * OUT_HEAD + t] + adst));
        float sum = 0.f;
        for (int j = beg; j < end; j++)
            sum += expf(leaky(g_A2s[g_esrc[j] * OUT_HEAD + t] + adst) - mx);
        sm_m[t] = mx;
        sm_inv[t] = 1.0f / (sum + GAT_EPS);
    }
    __syncthreads();

    float acc[OUT_HEAD] = {0.f, 0.f, 0.f, 0.f, 0.f};
    for (int jb = beg; jb < end; jb += 16) {
        int cnt = min(16, end - jb);
        if (t < cnt) srcb[t] = g_esrc[jb + t];
        __syncthreads();
        if (t < cnt * OUT_HEAD) {
            int j = t / OUT_HEAD, hh = t % OUT_HEAD;
            int s = srcb[j];
            float e = leaky(g_A2s[s * OUT_HEAD + hh] + g_A2d[n * OUT_HEAD + hh]);
            alpha[j][hh] = expf(e - sm_m[hh]) * sm_inv[hh];
        }
        __syncthreads();
        for (int j = 0; j < cnt; j++) {
            const f16* row = g_H2h + (size_t)srcb[j] * F2;
#pragma unroll
            for (int hh = 0; hh < OUT_HEAD; hh++)
                acc[hh] += alpha[j][hh] * __half2float(row[hh * OUT_FEAT + t]);
        }
        __syncthreads();
    }
    float o = (acc[0] + acc[1] + acc[2] + acc[3] + acc[4]) * 0.2f + b2[t];
    atomicAdd(&g_part[(n & 31) * OUT_FEAT + t], o);
}

// ---------------- Final node-mean + tanh ----------------
__global__ void k_final(float* __restrict__ out) {
    int c = threadIdx.x;
    float s = 0.f;
#pragma unroll
    for (int b = 0; b < 32; b++) s += g_part[b * OUT_FEAT + c];
    out[c] = tanhf(s / (float)N_NODES);
}

// ---------------- Launch ----------------
extern "C" void kernel_launch(void* const* d_in, const int* in_sizes, int n_in,
                              void* d_out, int out_size) {
    const float* x        = (const float*)d_in[0];
    const void*  ei       = d_in[1];
    const float* W1       = (const float*)d_in[2];
    const float* att_src1 = (const float*)d_in[3];
    const float* att_dst1 = (const float*)d_in[4];
    const float* b1       = (const float*)d_in[5];
    const float* W2       = (const float*)d_in[6];
    const float* att_src2 = (const float*)d_in[7];
    const float* att_dst2 = (const float*)d_in[8];
    const float* b2       = (const float*)d_in[9];
    float* out = (float*)d_out;

    static f16*   s_H1h  = nullptr;
    static float* s_Pk   = nullptr;
    static f16*   s_xh   = nullptr;
    static f16*   s_W1h  = nullptr;
    static f16*   s_H1ae = nullptr;
    static f16*   s_W2h  = nullptr;
    static cudaStream_t s2 = nullptr;
    static cudaEvent_t  evFork = nullptr, evJoin = nullptr;
    static bool   s_init = false;
    if (!s_init) {
        cudaGetSymbolAddress((void**)&s_H1h,  g_H1h);
        cudaGetSymbolAddress((void**)&s_Pk,   g_Pk);
        cudaGetSymbolAddress((void**)&s_xh,   g_xh);
        cudaGetSymbolAddress((void**)&s_W1h,  g_W1h);
        cudaGetSymbolAddress((void**)&s_H1ae, g_H1ae);
        cudaGetSymbolAddress((void**)&s_W2h,  g_W2h);
        cudaFuncSetAttribute(hgemm1, cudaFuncAttributeMaxDynamicSharedMemorySize, HG_SMEM);
        cudaFuncSetAttribute(hgemm2, cudaFuncAttributeMaxDynamicSharedMemorySize, HG2_SMEM);
        cudaStreamCreateWithFlags(&s2, cudaStreamNonBlocking);
        cudaEventCreateWithFlags(&evFork, cudaEventDisableTiming);
        cudaEventCreateWithFlags(&evJoin, cudaEventDisableTiming);
        s_init = true;
    }

    // ---- fork: CSR chain + W2 convert on s2, concurrent with GEMM1 path ----
    cudaEventRecord(evFork, 0);
    cudaStreamWaitEvent(s2, evFork, 0);

    k_init   <<<(N_NODES + 256) / 256, 256, 0, s2>>>((const int*)ei);
    k_count  <<<(E2 + 255) / 256, 256, 0, s2>>>(ei);
    k_scan   <<<1, 1024, 0, s2>>>();
    k_scatter<<<(E2 + 255) / 256, 256, 0, s2>>>(ei);
    k_cvt_W2 <<<((F1 * F2 / 4) + 255) / 256, 256, 0, s2>>>(W2);
    cudaEventRecord(evJoin, s2);

    // ---- main stream: merged x/W1 convert (also zeroes A1s/A1d/g_part) ----
    k_cvt_xw1<<<(2 * N_NODES * IN_FEAT / 4) / 256, 256>>>(x, W1);

    // GEMM1: H1h = x_f16 @ W1_f16, K=256, fp16 out + fused layer-1 dots
    hgemm1<<<dim3(F1 / BN, N_NODES / BM), 256, HG_SMEM>>>(
        s_xh, s_W1h, s_H1h, F1, IN_FEAT, IN_FEAT, att_src1, att_dst1);

    // ---- join: agg1 needs CSR; GEMM2 needs W2h ----
    cudaStreamWaitEvent(0, evJoin, 0);

    k_agg1<<<N_NODES, 256>>>(b1);

    // GEMM2: 64x64 warp tiles, BK=64, split-K=4, kLen=1024 (640 CTAs)
    hgemm2<<<dim3(F2 / BN, N_NODES / BM, KSPLIT), 128, HG2_SMEM>>>(
        s_H1ae, s_W2h, s_Pk, (size_t)N_NODES * F2, F2, F1, F1 / KSPLIT);

    // fused: H2h = sum(Pk) (fp16) + layer-2 attention dots
    k_red_dots2<<<N_NODES, 160>>>(att_src2, att_dst2);

    // agg2 with fused partial node-sum (atomicAdd into g_part)
    k_agg2<<<N_NODES, 128>>>(b2);

    k_final<<<1, 128>>>(out);
}

// round 17
// speedup vs baseline: 1.6730x; 1.0205x over previous
#include <cuda_runtime.h>
#include <cuda_fp16.h>
#include <stdint.h>
#include <math.h>

typedef __half f16;

// ---------------- Problem constants ----------------
#define N_NODES 4096
#define N_EDGES 32768
#define E2      (N_EDGES + N_NODES)   // with self loops = 36864
#define IN_FEAT 256
#define HID     64
#define IN_HEAD 64
#define OUT_FEAT 128
#define OUT_HEAD 5
#define F1      (IN_HEAD * HID)       // 4096
#define F2      (OUT_HEAD * OUT_FEAT) // 640
#define NEG_SLOPE 0.2f
#define GAT_EPS 1e-16f
#define KSPLIT  4

// ---------------- Device scratch ----------------
__device__ int   g_is64;
__device__ int   g_counts[N_NODES + 1];
__device__ int   g_offs[N_NODES + 1];
__device__ int   g_cursor[N_NODES];
__device__ int   g_esrc[E2];
__device__ f16   g_H1h[(size_t)N_NODES * F1];     // x @ W1 in fp16 (32 MB)
__device__ float g_A1s[(size_t)N_NODES * IN_HEAD];
__device__ float g_A1d[(size_t)N_NODES * IN_HEAD];
__device__ float g_Pk [(size_t)KSPLIT * N_NODES * F2];  // split-K partials (40 MB)
__device__ f16   g_H2h[(size_t)N_NODES * F2];     // H1a @ W2 in fp16 (5 MB)
__device__ float g_A2s[(size_t)N_NODES * OUT_HEAD];
__device__ float g_A2d[(size_t)N_NODES * OUT_HEAD];
__device__ float g_part[32 * OUT_FEAT];

// fp16 operands
__device__ f16   g_xh  [(size_t)N_NODES * IN_FEAT]; // 2 MB
__device__ f16   g_W1h [(size_t)IN_FEAT * F1];      // 2 MB
__device__ f16   g_H1ae[(size_t)N_NODES * F1];      // 32 MB (elu(agg1+b1) fp16)
__device__ f16   g_W2h [(size_t)F1 * F2];           // 5.2 MB

// ---------------- init: zero counts + int64/int32 detect ----------------
__global__ void k_init(const int* ei32) {
    int i = blockIdx.x * blockDim.x + threadIdx.x;
    if (i <= N_NODES) g_counts[i] = 0;
    if (blockIdx.x == 0 && threadIdx.x < 32) {
        int v = ei32[2 * threadIdx.x + 1];
        unsigned any = __ballot_sync(0xffffffffu, v != 0);
        if (threadIdx.x == 0) g_is64 = (any == 0) ? 1 : 0;
    }
}

__device__ __forceinline__ int load_ei(const void* ei, int idx) {
    if (g_is64) return (int)((const long long*)ei)[idx];
    return ((const int*)ei)[idx];
}

// ---------------- CSR build ----------------
__global__ void k_count(const void* ei) {
    int i = blockIdx.x * blockDim.x + threadIdx.x;
    if (i >= E2) return;
    int dst = (i < N_EDGES) ? load_ei(ei, N_EDGES + i) : (i - N_EDGES);
    atomicAdd(&g_counts[dst], 1);
}

__global__ void k_scan() {   // 1 block, 1024 threads; scan 4096 counts
    __shared__ int buf[2][1024];
    int t = threadIdx.x;
    int c0 = g_counts[4 * t], c1 = g_counts[4 * t + 1];
    int c2 = g_counts[4 * t + 2], c3 = g_counts[4 * t + 3];
    int s = c0 + c1 + c2 + c3;
    buf[0][t] = s;
    __syncthreads();
    int pin = 0;
    for (int off = 1; off < 1024; off <<= 1) {
        int v = buf[pin][t];
        if (t >= off) v += buf[pin][t - off];
        buf[pin ^ 1][t] = v;
        pin ^= 1;
        __syncthreads();
    }
    int incl = buf[pin][t];
    int base = incl - s;
    g_offs[4 * t]     = base;
    g_offs[4 * t + 1] = base + c0;
    g_offs[4 * t + 2] = base + c0 + c1;
    g_offs[4 * t + 3] = base + c0 + c1 + c2;
    g_cursor[4 * t]     = base;
    g_cursor[4 * t + 1] = base + c0;
    g_cursor[4 * t + 2] = base + c0 + c1;
    g_cursor[4 * t + 3] = base + c0 + c1 + c2;
    if (t == 1023) g_offs[N_NODES] = incl;
}

__global__ void k_scatter(const void* ei) {
    int i = blockIdx.x * blockDim.x + threadIdx.x;
    if (i >= E2) return;
    int src, dst;
    if (i < N_EDGES) { src = load_ei(ei, i); dst = load_ei(ei, N_EDGES + i); }
    else             { src = i - N_EDGES;    dst = i - N_EDGES; }
    int pos = atomicAdd(&g_cursor[dst], 1);
    g_esrc[pos] = src;
}

// ---------------- fp16 convert kernels (vectorized) ----------------
// Merged x + W1 convert; also zero-inits A1s/A1d and g_part each replay.
__global__ void k_cvt_xw1(const float* __restrict__ x, const float* __restrict__ W1) {
    int i = blockIdx.x * blockDim.x + threadIdx.x;   // 524288 threads
    const int NX = N_NODES * IN_FEAT / 4;            // 262144 float4s
    if (i < NX) {
        float4 v = ((const float4*)x)[i];
        __half2* o = (__half2*)g_xh;
        o[2 * i]     = __floats2half2_rn(v.x, v.y);
        o[2 * i + 1] = __floats2half2_rn(v.z, v.w);
        g_A1s[i] = 0.f;                              // N_NODES*IN_HEAD == 262144
        g_A1d[i] = 0.f;
        if (i < 32 * OUT_FEAT) g_part[i] = 0.f;
    } else {
        int j = i - NX;                              // 262144 float4s of W1
        float4 v = ((const float4*)W1)[j];
        __half2* o = (__half2*)g_W1h;
        o[2 * j]     = __floats2half2_rn(v.x, v.y);
        o[2 * j + 1] = __floats2half2_rn(v.z, v.w);
    }
}

__global__ void k_cvt_W2(const float* __restrict__ W) {
    int i = blockIdx.x * blockDim.x + threadIdx.x;
    if (i >= (F1 * F2) / 4) return;
    float4 v = ((const float4*)W)[i];
    __half2* o = (__half2*)g_W2h;
    o[2 * i]     = __floats2half2_rn(v.x, v.y);
    o[2 * i + 1] = __floats2half2_rn(v.z, v.w);
}

// ---------------- shared GEMM geometry ----------------
#define BM 128
#define BN 128
#define BK 32
#define STG 3
#define APITCH (BK + 8)
#define BPITCH (BN + 8)
#define HG_SMEM (STG * (BM * APITCH + BK * BPITCH) * 2)

// GEMM2 geometry: BK=32, 4 stages (deeper prefetch)
#define STG2 4
#define HG2_SMEM (STG2 * (BM * APITCH + BK * BPITCH) * 2)   // 75776 B

// ---------------- GEMM1: 8 warps, warp tile 64x32, fp16 out + fused dots1 ----------------
__global__ __launch_bounds__(256, 2)
void hgemm1(const f16* __restrict__ A, const f16* __restrict__ B,
            f16* __restrict__ C, int N, int aStride, int kLen,
            const float* __restrict__ att_src, const float* __restrict__ att_dst) {
    extern __shared__ f16 smbuf[];
    f16* sA = smbuf;
    f16* sB = smbuf + STG * BM * APITCH;
    int t = threadIdx.x, lane = t & 31, warp = t >> 5;
    int wm = (warp >> 2) * 64;
    int wn = (warp & 3) * 32;
    int bx = blockIdx.x, by = blockIdx.y;
    const f16* Ab = A + (size_t)(by * BM) * aStride;
    const f16* Bb = B + bx * BN;

    int a_row = t >> 2;
    int a_col = (t & 3) * 8;
    int b_row = t >> 4;
    int b_col = (t & 15) * 8;

    float acc[4][4][4];
#pragma unroll
    for (int i = 0; i < 4; i++)
#pragma unroll
        for (int j = 0; j < 4; j++)
#pragma unroll
            for (int r = 0; r < 4; r++) acc[i][j][r] = 0.f;

    auto issue = [&](int j) {
        int buf = j % STG;
        int k0 = j * BK;
        f16* pa = sA + buf * BM * APITCH;
        f16* pb = sB + buf * BK * BPITCH;
        uint32_t da0 = (uint32_t)__cvta_generic_to_shared(pa + a_row * APITCH + a_col);
        uint32_t da1 = (uint32_t)__cvta_generic_to_shared(pa + (a_row + 64) * APITCH + a_col);
        const f16* ga0 = Ab + (size_t)a_row * aStride + k0 + a_col;
        const f16* ga1 = Ab + (size_t)(a_row + 64) * aStride + k0 + a_col;
        asm volatile("cp.async.cg.shared.global [%0], [%1], 16;" :: "r"(da0), "l"(ga0));
        asm volatile("cp.async.cg.shared.global [%0], [%1], 16;" :: "r"(da1), "l"(ga1));
        uint32_t db0 = (uint32_t)__cvta_generic_to_shared(pb + b_row * BPITCH + b_col);
        uint32_t db1 = (uint32_t)__cvta_generic_to_shared(pb + (b_row + 16) * BPITCH + b_col);
        const f16* gb0 = Bb + (size_t)(k0 + b_row) * N + b_col;
        const f16* gb1 = Bb + (size_t)(k0 + b_row + 16) * N + b_col;
        asm volatile("cp.async.cg.shared.global [%0], [%1], 16;" :: "r"(db0), "l"(gb0));
        asm volatile("cp.async.cg.shared.global [%0], [%1], 16;" :: "r"(db1), "l"(gb1));
        asm volatile("cp.async.commit_group;");
    };

    int nc = kLen / BK;
    issue(0);
    if (nc > 1) issue(1);
    for (int s = 0; s < nc; s++) {
        if (s < nc - 1) { asm volatile("cp.async.wait_group 1;"); }
        else            { asm volatile("cp.async.wait_group 0;"); }
        __syncthreads();
        if (s + 2 < nc) issue(s + 2);
        int buf = s % STG;
        f16* pa = sA + buf * BM * APITCH;
        f16* pb = sB + buf * BK * BPITCH;
#pragma unroll
        for (int kk = 0; kk < 2; kk++) {
            int k = kk * 16;
            uint32_t ar[4][4], br[2][4];
#pragma unroll
            for (int mi = 0; mi < 4; mi++) {
                int row = wm + mi * 16 + (lane & 7) + ((lane >> 3) & 1) * 8;
                int col = k + (lane >> 4) * 8;
                uint32_t addr = (uint32_t)__cvta_generic_to_shared(pa + row * APITCH + col);
                asm volatile("ldmatrix.sync.aligned.m8n8.x4.shared.b16 {%0,%1,%2,%3}, [%4];"
                             : "=r"(ar[mi][0]), "=r"(ar[mi][1]), "=r"(ar[mi][2]), "=r"(ar[mi][3])
                             : "r"(addr));
            }
#pragma unroll
            for (int n2 = 0; n2 < 2; n2++) {
                int rrow = k + (lane & 7) + ((lane >> 3) & 1) * 8;
                int rcol = wn + n2 * 16 + (lane >> 4) * 8;
                uint32_t addr = (uint32_t)__cvta_generic_to_shared(pb + rrow * BPITCH + rcol);
                asm volatile("ldmatrix.sync.aligned.m8n8.x4.trans.shared.b16 {%0,%1,%2,%3}, [%4];"
                             : "=r"(br[n2][0]), "=r"(br[n2][1]), "=r"(br[n2][2]), "=r"(br[n2][3])
                             : "r"(addr));
            }
#pragma unroll
            for (int mi = 0; mi < 4; mi++)
#pragma unroll
                for (int ni = 0; ni < 4; ni++) {
                    uint32_t b0 = br[ni >> 1][(ni & 1) * 2];
                    uint32_t b1 = br[ni >> 1][(ni & 1) * 2 + 1];
                    asm volatile(
                        "mma.sync.aligned.m16n8k16.row.col.f32.f16.f16.f32 "
                        "{%0,%1,%2,%3}, {%4,%5,%6,%7}, {%8,%9}, {%0,%1,%2,%3};"
                        : "+f"(acc[mi][ni][0]), "+f"(acc[mi][ni][1]),
                          "+f"(acc[mi][ni][2]), "+f"(acc[mi][ni][3])
                        : "r"(ar[mi][0]), "r"(ar[mi][1]), "r"(ar[mi][2]), "r"(ar[mi][3]),
                          "r"(b0), "r"(b1));
                }
        }
        __syncthreads();
    }
    f16* Cb = C + (size_t)(by * BM + wm) * N + bx * BN + wn;
#pragma unroll
    for (int mi = 0; mi < 4; mi++)
#pragma unroll
        for (int ni = 0; ni < 4; ni++) {
            int r0 = mi * 16 + (lane >> 2);
            int c0 = ni * 8 + (lane & 3) * 2;
            *(__half2*)(Cb + (size_t)r0 * N + c0)       = __floats2half2_rn(acc[mi][ni][0], acc[mi][ni][1]);
            *(__half2*)(Cb + (size_t)(r0 + 8) * N + c0) = __floats2half2_rn(acc[mi][ni][2], acc[mi][ni][3]);
        }
    // ---- fused layer-1 attention dots (warp's 32 cols lie in one head) ----
    int gcol0 = bx * BN + wn;
    int head = gcol0 >> 6;               // HID = 64
    const float* as = att_src + head * HID;
    const float* ad = att_dst + head * HID;
    int cbase = (gcol0 & 63) + (lane & 3) * 2;
#pragma unroll
    for (int mi = 0; mi < 4; mi++) {
#pragma unroll
        for (int rr = 0; rr < 2; rr++) {
            float ssum = 0.f, dsum = 0.f;
#pragma unroll
            for (int ni = 0; ni < 4; ni++) {
#pragma unroll
                for (int q = 0; q < 2; q++) {
                    int ch = cbase + ni * 8 + q;
                    float v = acc[mi][ni][rr * 2 + q];
                    ssum += v * as[ch];
                    dsum += v * ad[ch];
                }
            }
            ssum += __shfl_xor_sync(0xffffffffu, ssum, 1);
            ssum += __shfl_xor_sync(0xffffffffu, ssum, 2);
            dsum += __shfl_xor_sync(0xffffffffu, dsum, 1);
            dsum += __shfl_xor_sync(0xffffffffu, dsum, 2);
            if ((lane & 3) == 0) {
                int n = by * BM + wm + mi * 16 + (lane >> 2) + rr * 8;
                atomicAdd(&g_A1s[n * IN_HEAD + head], ssum);
                atomicAdd(&g_A1d[n * IN_HEAD + head], dsum);
            }
        }
    }
}

// ---------------- GEMM2: 4 warps, warp tile 64x64, BK=32, 4-stage pipeline, fp32 out ----------------
__global__ __launch_bounds__(128, 2)
void hgemm2(const f16* __restrict__ A, const f16* __restrict__ B,
            float* __restrict__ Cbase, size_t cStride,
            int N, int aStride, int kLen) {
    extern __shared__ f16 smbuf[];
    f16* sA = smbuf;                               // [STG2][128][APITCH]
    f16* sB = smbuf + STG2 * BM * APITCH;          // [STG2][32][BPITCH]
    int t = threadIdx.x, lane = t & 31, warp = t >> 5;
    int wm = (warp >> 1) * 64;   // 0 or 64
    int wn = (warp & 1) * 64;    // 0 or 64
    int bx = blockIdx.x, by = blockIdx.y, bz = blockIdx.z;
    int kOff = bz * kLen;
    const f16* Ab = A + (size_t)(by * BM) * aStride + kOff;
    const f16* Bb = B + (size_t)kOff * N + bx * BN;

    float acc[4][8][4];
#pragma unroll
    for (int i = 0; i < 4; i++)
#pragma unroll
        for (int j = 0; j < 8; j++)
#pragma unroll
            for (int r = 0; r < 4; r++) acc[i][j][r] = 0.f;

    auto issue = [&](int j) {
        int buf = j % STG2;
        int k0 = j * BK;
        f16* pa = sA + buf * BM * APITCH;
        f16* pb = sB + buf * BK * BPITCH;
#pragma unroll
        for (int i = 0; i < 4; i++) {          // A: 128x32 = 512 chunks of 16B
            int id = t + 128 * i;
            int row = id >> 2, c = (id & 3) * 8;
            uint32_t d = (uint32_t)__cvta_generic_to_shared(pa + row * APITCH + c);
            const f16* g = Ab + (size_t)row * aStride + k0 + c;
            asm volatile("cp.async.cg.shared.global [%0], [%1], 16;" :: "r"(d), "l"(g));
        }
#pragma unroll
        for (int i = 0; i < 4; i++) {          // B: 32x128 = 512 chunks of 16B
            int id = t + 128 * i;
            int row = id >> 4, c = (id & 15) * 8;
            uint32_t d = (uint32_t)__cvta_generic_to_shared(pb + row * BPITCH + c);
            const f16* g = Bb + (size_t)(k0 + row) * N + c;
            asm volatile("cp.async.cg.shared.global [%0], [%1], 16;" :: "r"(d), "l"(g));
        }
        asm volatile("cp.async.commit_group;");
    };

    int nc = kLen / BK;
    issue(0);
    if (nc > 1) issue(1);
    if (nc > 2) issue(2);
    for (int s = 0; s < nc; s++) {
        if (s + 2 < nc)      { asm volatile("cp.async.wait_group 2;"); }
        else if (s + 1 < nc) { asm volatile("cp.async.wait_group 1;"); }
        else                 { asm volatile("cp.async.wait_group 0;"); }
        __syncthreads();
        if (s + 3 < nc) issue(s + 3);
        int buf = s % STG2;
        f16* pa = sA + buf * BM * APITCH;
        f16* pb = sB + buf * BK * BPITCH;
#pragma unroll
        for (int kk = 0; kk < 2; kk++) {
            int k = kk * 16;
            uint32_t ar[4][4], br[4][4];
#pragma unroll
            for (int mi = 0; mi < 4; mi++) {
                int row = wm + mi * 16 + (lane & 7) + ((lane >> 3) & 1) * 8;
                int col = k + (lane >> 4) * 8;
                uint32_t addr = (uint32_t)__cvta_generic_to_shared(pa + row * APITCH + col);
                asm volatile("ldmatrix.sync.aligned.m8n8.x4.shared.b16 {%0,%1,%2,%3}, [%4];"
                             : "=r"(ar[mi][0]), "=r"(ar[mi][1]), "=r"(ar[mi][2]), "=r"(ar[mi][3])
                             : "r"(addr));
            }
#pragma unroll
            for (int n2 = 0; n2 < 4; n2++) {
                int rrow = k + (lane & 7) + ((lane >> 3) & 1) * 8;
                int rcol = wn + n2 * 16 + (lane >> 4) * 8;
                uint32_t addr = (uint32_t)__cvta_generic_to_shared(pb + rrow * BPITCH + rcol);
                asm volatile("ldmatrix.sync.aligned.m8n8.x4.trans.shared.b16 {%0,%1,%2,%3}, [%4];"
                             : "=r"(br[n2][0]), "=r"(br[n2][1]), "=r"(br[n2][2]), "=r"(br[n2][3])
                             : "r"(addr));
            }
#pragma unroll
            for (int mi = 0; mi < 4; mi++)
#pragma unroll
                for (int ni = 0; ni < 8; ni++) {
                    uint32_t b0 = br[ni >> 1][(ni & 1) * 2];
                    uint32_t b1 = br[ni >> 1][(ni & 1) * 2 + 1];
                    asm volatile(
                        "mma.sync.aligned.m16n8k16.row.col.f32.f16.f16.f32 "
                        "{%0,%1,%2,%3}, {%4,%5,%6,%7}, {%8,%9}, {%0,%1,%2,%3};"
                        : "+f"(acc[mi][ni][0]), "+f"(acc[mi][ni][1]),
                          "+f"(acc[mi][ni][2]), "+f"(acc[mi][ni][3])
                        : "r"(ar[mi][0]), "r"(ar[mi][1]), "r"(ar[mi][2]), "r"(ar[mi][3]),
                          "r"(b0), "r"(b1));
                }
        }
        __syncthreads();
    }
    float* Cb = Cbase + bz * cStride + (size_t)(by * BM + wm) * N + bx * BN + wn;
#pragma unroll
    for (int mi = 0; mi < 4; mi++)
#pragma unroll
        for (int ni = 0; ni < 8; ni++) {
            int r0 = mi * 16 + (lane >> 2);
            int c0 = ni * 8 + (lane & 3) * 2;
            *(float2*)(Cb + (size_t)r0 * N + c0)       = make_float2(acc[mi][ni][0], acc[mi][ni][1]);
            *(float2*)(Cb + (size_t)(r0 + 8) * N + c0) = make_float2(acc[mi][ni][2], acc[mi][ni][3]);
        }
}

// ---------------- fused split-K reduce (4-way) + fp16 H2 store + layer-2 dots ----------------
__global__ void k_red_dots2(const float* __restrict__ att_src, const float* __restrict__ att_dst) {
    int n = blockIdx.x;
    int t = threadIdx.x, lane = t & 31, h = t >> 5;
    const size_t stride4 = (size_t)N_NODES * F2 / 4;
    const float4* p = (const float4*)g_Pk + (size_t)n * (F2 / 4);

    float4 v = p[t];
#pragma unroll
    for (int z = 1; z < KSPLIT; z++) {
        float4 a = p[z * stride4 + t];
        v.x += a.x; v.y += a.y; v.z += a.z; v.w += a.w;
    }
    __half2* h2 = (__half2*)g_H2h + (size_t)n * (F2 / 2);
    h2[2 * t]     = __floats2half2_rn(v.x, v.y);
    h2[2 * t + 1] = __floats2half2_rn(v.z, v.w);

    int c0 = lane * 4;
    const float* as = att_src + h * OUT_FEAT + c0;
    const float* ad = att_dst + h * OUT_FEAT + c0;
    float sa = v.x * as[0] + v.y * as[1] + v.z * as[2] + v.w * as[3];
    float sd = v.x * ad[0] + v.y * ad[1] + v.z * ad[2] + v.w * ad[3];
#pragma unroll
    for (int o = 16; o > 0; o >>= 1) {
        sa += __shfl_xor_sync(0xffffffffu, sa, o);
        sd += __shfl_xor_sync(0xffffffffu, sd, o);
    }
    if (lane == 0) {
        g_A2s[n * OUT_HEAD + h] = sa;
        g_A2d[n * OUT_HEAD + h] = sd;
    }
}

__device__ __forceinline__ float leaky(float x) { return x > 0.f ? x : NEG_SLOPE * x; }

// ---------------- Layer-1 softmax + aggregation + bias + elu -> fp16 ----------------
__global__ void k_agg1(const float* __restrict__ b1) {
    int n = blockIdx.x;
    int t = threadIdx.x;
    int h = t & 63, slot = t >> 6;
    int beg = g_offs[n], end = g_offs[n + 1];
    float adst = g_A1d[n * IN_HEAD + h];

    __shared__ float red[4][64];
    __shared__ float sm_m[64], sm_inv[64];
    __shared__ int   srcb[32];
    __shared__ float alpha[32][64];

    float mx = -1e30f;
    for (int j = beg + slot; j < end; j += 4) {
        int s = g_esrc[j];
        mx = fmaxf(mx, leaky(g_A1s[s * IN_HEAD + h] + adst));
    }
    red[slot][h] = mx;
    __syncthreads();
    if (slot == 0) {
        sm_m[h] = fmaxf(fmaxf(red[0][h], red[1][h]), fmaxf(red[2][h], red[3][h]));
    }
    __syncthreads();
    float M = sm_m[h];

    float sum = 0.f;
    for (int j = beg + slot; j < end; j += 4) {
        int s = g_esrc[j];
        sum += expf(leaky(g_A1s[s * IN_HEAD + h] + adst) - M);
    }
    red[slot][h] = sum;
    __syncthreads();
    if (slot == 0) {
        float d = red[0][h] + red[1][h] + red[2][h] + red[3][h];
        sm_inv[h] = 1.0f / (d + GAT_EPS);
    }
    __syncthreads();
    float INV = sm_inv[h];

    int c2 = t & 31, g = t >> 5;   // half2 pair, head group of 8
    float2 acc[8];
#pragma unroll
    for (int k = 0; k < 8; k++) acc[k] = make_float2(0.f, 0.f);

    for (int jb = beg; jb < end; jb += 32) {
        int cnt = min(32, end - jb);
        if (t < cnt) srcb[t] = g_esrc[jb + t];
        __syncthreads();
        for (int j = slot; j < cnt; j += 4) {
            int s = srcb[j];
            float e = leaky(g_A1s[s * IN_HEAD + h] + adst);
            alpha[j][h] = expf(e - M) * INV;
        }
        __syncthreads();
        int j = 0;
        for (; j + 3 < cnt; j += 4) {
            const __half2* r0 = (const __half2*)(g_H1h + (size_t)srcb[j] * F1);
            const __half2* r1 = (const __half2*)(g_H1h + (size_t)srcb[j + 1] * F1);
            const __half2* r2 = (const __half2*)(g_H1h + (size_t)srcb[j + 2] * F1);
            const __half2* r3 = (const __half2*)(g_H1h + (size_t)srcb[j + 3] * F1);
#pragma unroll
            for (int k = 0; k < 8; k++) {
                int hh = g * 8 + k;
                int idx = hh * 32 + c2;
                float2 f0 = __half22float2(r0[idx]);
                float2 f1 = __half22float2(r1[idx]);
                float2 f2 = __half22float2(r2[idx]);
                float2 f3 = __half22float2(r3[idx]);
                float a0 = alpha[j][hh], a1 = alpha[j + 1][hh];
                float a2 = alpha[j + 2][hh], a3 = alpha[j + 3][hh];
                acc[k].x += a0 * f0.x + a1 * f1.x + a2 * f2.x + a3 * f3.x;
                acc[k].y += a0 * f0.y + a1 * f1.y + a2 * f2.y + a3 * f3.y;
            }
        }
        for (; j < cnt; j++) {
            const __half2* row = (const __half2*)(g_H1h + (size_t)srcb[j] * F1);
#pragma unroll
            for (int k = 0; k < 8; k++) {
                int hh = g * 8 + k;
                float2 f = __half22float2(row[hh * 32 + c2]);
                float a = alpha[j][hh];
                acc[k].x += a * f.x;
                acc[k].y += a * f.y;
            }
        }
        __syncthreads();
    }
    __half2* rowo = (__half2*)(g_H1ae + (size_t)n * F1);
#pragma unroll
    for (int k = 0; k < 8; k++) {
        int hh = g * 8 + k;
        float vx = acc[k].x + b1[hh * HID + 2 * c2];
        float vy = acc[k].y + b1[hh * HID + 2 * c2 + 1];
        vx = vx > 0.f ? vx : expm1f(vx);
        vy = vy > 0.f ? vy : expm1f(vy);
        rowo[hh * 32 + c2] = __floats2half2_rn(vx, vy);
    }
}

// ---------------- Layer-2 softmax + aggregation + head-mean + bias + fused node-sum ----------------
__global__ void k_agg2(const float* __restrict__ b2) {
    int n = blockIdx.x;
    int t = threadIdx.x;
    int beg = g_offs[n], end = g_offs[n + 1];

    __shared__ float sm_m[OUT_HEAD], sm_inv[OUT_HEAD];
    __shared__ int   srcb[32];
    __shared__ float alpha[32][OUT_HEAD];

    if (t < OUT_HEAD) {
        float adst = g_A2d[n * OUT_HEAD + t];
        float mx = -1e30f;
        for (int j = beg; j < end; j++)
            mx = fmaxf(mx, leaky(g_A2s[g_esrc[j] * OUT_HEAD + t] + adst));
        float sum = 0.f;
        for (int j = beg; j < end; j++)
            sum += expf(leaky(g_A2s[g_esrc[j] * OUT_HEAD + t] + adst) - mx);
        sm_m[t] = mx;
        sm_inv[t] = 1.0f / (sum + GAT_EPS);
    }
    __syncthreads();

    float acc[OUT_HEAD] = {0.f, 0.f, 0.f, 0.f, 0.f};
    for (int jb = beg; jb < end; jb += 32) {
        int cnt = min(32, end - jb);
        if (t < cnt) srcb[t] = g_esrc[jb + t];
        __syncthreads();
        for (int u = t; u < cnt * OUT_HEAD; u += 128) {
            int j = u / OUT_HEAD, hh = u % OUT_HEAD;
            int s = srcb[j];
            float e = leaky(g_A2s[s * OUT_HEAD + hh] + g_A2d[n * OUT_HEAD + hh]);
            alpha[j][hh] = expf(e - sm_m[hh]) * sm_inv[hh];
        }
        __syncthreads();
        for (int j = 0; j < cnt; j++) {
            const f16* row = g_H2h + (size_t)srcb[j] * F2;
#pragma unroll
            for (int hh = 0; hh < OUT_HEAD; hh++)
                acc[hh] += alpha[j][hh] * __half2float(row[hh * OUT_FEAT + t]);
        }
        __syncthreads();
    }
    float o = (acc[0] + acc[1] + acc[2] + acc[3] + acc[4]) * 0.2f + b2[t];
    atomicAdd(&g_part[(n & 31) * OUT_FEAT + t], o);
}

// ---------------- Final node-mean + tanh ----------------
__global__ void k_final(float* __restrict__ out) {
    int c = threadIdx.x;
    float s = 0.f;
#pragma unroll
    for (int b = 0; b < 32; b++) s += g_part[b * OUT_FEAT + c];
    out[c] = tanhf(s / (float)N_NODES);
}

// ---------------- Launch ----------------
extern "C" void kernel_launch(void* const* d_in, const int* in_sizes, int n_in,
                              void* d_out, int out_size) {
    const float* x        = (const float*)d_in[0];
    const void*  ei       = d_in[1];
    const float* W1       = (const float*)d_in[2];
    const float* att_src1 = (const float*)d_in[3];
    const float* att_dst1 = (const float*)d_in[4];
    const float* b1       = (const float*)d_in[5];
    const float* W2       = (const float*)d_in[6];
    const float* att_src2 = (const float*)d_in[7];
    const float* att_dst2 = (const float*)d_in[8];
    const float* b2       = (const float*)d_in[9];
    float* out = (float*)d_out;

    static f16*   s_H1h  = nullptr;
    static float* s_Pk   = nullptr;
    static f16*   s_xh   = nullptr;
    static f16*   s_W1h  = nullptr;
    static f16*   s_H1ae = nullptr;
    static f16*   s_W2h  = nullptr;
    static cudaStream_t s2 = nullptr;
    static cudaEvent_t  evFork = nullptr, evJoin = nullptr;
    static bool   s_init = false;
    if (!s_init) {
        cudaGetSymbolAddress((void**)&s_H1h,  g_H1h);
        cudaGetSymbolAddress((void**)&s_Pk,   g_Pk);
        cudaGetSymbolAddress((void**)&s_xh,   g_xh);
        cudaGetSymbolAddress((void**)&s_W1h,  g_W1h);
        cudaGetSymbolAddress((void**)&s_H1ae, g_H1ae);
        cudaGetSymbolAddress((void**)&s_W2h,  g_W2h);
        cudaFuncSetAttribute(hgemm1, cudaFuncAttributeMaxDynamicSharedMemorySize, HG_SMEM);
        cudaFuncSetAttribute(hgemm2, cudaFuncAttributeMaxDynamicSharedMemorySize, HG2_SMEM);
        cudaStreamCreateWithFlags(&s2, cudaStreamNonBlocking);
        cudaEventCreateWithFlags(&evFork, cudaEventDisableTiming);
        cudaEventCreateWithFlags(&evJoin, cudaEventDisableTiming);
        s_init = true;
    }

    // ---- fork: CSR chain + W2 convert on s2, concurrent with GEMM1 path ----
    cudaEventRecord(evFork, 0);
    cudaStreamWaitEvent(s2, evFork, 0);

    k_init   <<<(N_NODES + 256) / 256, 256, 0, s2>>>((const int*)ei);
    k_count  <<<(E2 + 255) / 256, 256, 0, s2>>>(ei);
    k_scan   <<<1, 1024, 0, s2>>>();
    k_scatter<<<(E2 + 255) / 256, 256, 0, s2>>>(ei);
    k_cvt_W2 <<<((F1 * F2 / 4) + 255) / 256, 256, 0, s2>>>(W2);
    cudaEventRecord(evJoin, s2);

    // ---- main stream: merged x/W1 convert (also zeroes A1s/A1d/g_part) ----
    k_cvt_xw1<<<(2 * N_NODES * IN_FEAT / 4) / 256, 256>>>(x, W1);

    // GEMM1: H1h = x_f16 @ W1_f16, K=256, fp16 out + fused layer-1 dots
    hgemm1<<<dim3(F1 / BN, N_NODES / BM), 256, HG_SMEM>>>(
        s_xh, s_W1h, s_H1h, F1, IN_FEAT, IN_FEAT, att_src1, att_dst1);

    // ---- join: agg1 needs CSR; GEMM2 needs W2h ----
    cudaStreamWaitEvent(0, evJoin, 0);

    k_agg1<<<N_NODES, 256>>>(b1);

    // GEMM2: 64x64 warp tiles, BK=32, 4-stage pipeline, split-K=4 (640 CTAs)
    hgemm2<<<dim3(F2 / BN, N_NODES / BM, KSPLIT), 128, HG2_SMEM>>>(
        s_H1ae, s_W2h, s_Pk, (size_t)N_NODES * F2, F2, F1, F1 / KSPLIT);

    // fused: H2h = sum(Pk) (fp16) + layer-2 attention dots
    k_red_dots2<<<N_NODES, 160>>>(att_src2, att_dst2);

    // agg2 with fused partial node-sum (atomicAdd into g_part)
    k_agg2<<<N_NODES, 128>>>(b2);

    k_final<<<1, 128>>>(out);
}